// round 1
// baseline (speedup 1.0000x reference)
#include <cuda_runtime.h>
#include <math.h>
#include <stdint.h>

#define S_LEN   2048
#define BATCH   2
#define HDIM    2048
#define NHEADS  16
#define HEADD   128
#define MROWS   (BATCH * S_LEN)   // 4096

// ---------------- scratch (static device allocations are allowed) ----------
__device__ float g_wcat[HDIM * 1536];     // [Wkv_d | Wq_d | Wrk]
__device__ float g_p1[MROWS * 1536];      // hs @ Wcat : [kv_d | q_d | k_r]
__device__ float g_q[MROWS * HDIM];       // q in [m][h*128+d] layout
__device__ float g_k[MROWS * HDIM];       // k in [m][h*128+d] layout
__device__ float g_v[MROWS * HDIM];       // v in [m][h*128+d] layout
__device__ float g_qr[MROWS * 1024];      // raw q_r before rope
__device__ float g_y[MROWS * HDIM];       // attention output

// ---------------- weight concat ----------------
__global__ void concat_w_kernel(const float* __restrict__ Wkv,
                                const float* __restrict__ Wq,
                                const float* __restrict__ Wrk) {
    int idx = blockIdx.x * blockDim.x + threadIdx.x;
    if (idx >= HDIM * 1536) return;
    int row = idx / 1536;
    int col = idx - row * 1536;
    float v;
    if (col < 256)      v = Wkv[row * 256 + col];
    else if (col < 512) v = Wq[row * 256 + (col - 256)];
    else                v = Wrk[row * 1024 + (col - 512)];
    g_wcat[idx] = v;
}

// ---------------- SGEMM 128x128x16, 8x8 micro-tile ----------------
// C[M,N] = A[M,K] @ B[K,N], all fp32 row-major with leading dims.
// SPLIT epilogue: col' = (n/64)*128 + (n%64) + coff  (interleave into head layout)
template<bool SPLIT>
__global__ void __launch_bounds__(256) sgemm128_kernel(
    const float* __restrict__ A, int lda,
    const float* __restrict__ B, int ldb,
    float* __restrict__ C, int ldc,
    int K, int coff)
{
    __shared__ float As[16][132];   // transposed A tile, padded
    __shared__ float Bs[16][128];

    const int bm = blockIdx.y * 128;
    const int bn = blockIdx.x * 128;
    const int tid = threadIdx.x;
    const int tx = tid & 15;
    const int ty = tid >> 4;

    float acc[8][8];
#pragma unroll
    for (int i = 0; i < 8; i++)
#pragma unroll
        for (int j = 0; j < 8; j++) acc[i][j] = 0.f;

    for (int k0 = 0; k0 < K; k0 += 16) {
        // A tile: 128x16, 512 float4, 2 per thread, store transposed
#pragma unroll
        for (int i = 0; i < 2; i++) {
            int f4 = tid + i * 256;
            int r  = f4 >> 2;
            int kq = f4 & 3;
            float4 v = *(const float4*)(A + (size_t)(bm + r) * lda + k0 + kq * 4);
            As[kq * 4 + 0][r] = v.x;
            As[kq * 4 + 1][r] = v.y;
            As[kq * 4 + 2][r] = v.z;
            As[kq * 4 + 3][r] = v.w;
        }
        // B tile: 16x128
#pragma unroll
        for (int i = 0; i < 2; i++) {
            int f4 = tid + i * 256;
            int rk = f4 >> 5;
            int c4 = f4 & 31;
            *(float4*)&Bs[rk][c4 * 4] =
                *(const float4*)(B + (size_t)(k0 + rk) * ldb + bn + c4 * 4);
        }
        __syncthreads();
#pragma unroll
        for (int k = 0; k < 16; k++) {
            float a[8], b[8];
            *(float4*)&a[0] = *(float4*)&As[k][ty * 8];
            *(float4*)&a[4] = *(float4*)&As[k][ty * 8 + 4];
            *(float4*)&b[0] = *(float4*)&Bs[k][tx * 8];
            *(float4*)&b[4] = *(float4*)&Bs[k][tx * 8 + 4];
#pragma unroll
            for (int i = 0; i < 8; i++)
#pragma unroll
                for (int j = 0; j < 8; j++) acc[i][j] += a[i] * b[j];
        }
        __syncthreads();
    }

#pragma unroll
    for (int i = 0; i < 8; i++) {
        int row = bm + ty * 8 + i;
#pragma unroll
        for (int j4 = 0; j4 < 8; j4 += 4) {
            int n = bn + tx * 8 + j4;
            int col = SPLIT ? (((n >> 6) << 7) + (n & 63) + coff) : n;
            float4 v = make_float4(acc[i][j4], acc[i][j4 + 1], acc[i][j4 + 2], acc[i][j4 + 3]);
            *(float4*)(C + (size_t)row * ldc + col) = v;
        }
    }
}

// ---------------- RoPE ----------------
// y=0: q_r from g_qr[m][h*64+j]  -> g_q[m][h*128+64+{j,j+32}]
// y=1: k_r from g_p1[m][512+h*64+j] -> g_k[m][h*128+64+{j,j+32}]
__global__ void rope_kernel() {
    int idx = blockIdx.x * blockDim.x + threadIdx.x;  // over 4096*16*32
    int isK = blockIdx.y;
    int m   = idx >> 9;
    int rem = idx & 511;
    int h   = rem >> 5;
    int j   = rem & 31;
    int s   = m & (S_LEN - 1);

    float inv = powf(10000.0f, -(float)j * (1.0f / 32.0f));
    float ang = (float)s * inv;
    float sn, cs;
    sincosf(ang, &sn, &cs);

    float x1, x2;
    float* dst;
    if (isK) {
        const float* src = g_p1 + (size_t)m * 1536 + 512 + h * 64;
        x1 = src[j]; x2 = src[j + 32];
        dst = g_k + (size_t)m * HDIM + h * HEADD + 64;
    } else {
        const float* src = g_qr + (size_t)m * 1024 + h * 64;
        x1 = src[j]; x2 = src[j + 32];
        dst = g_q + (size_t)m * HDIM + h * HEADD + 64;
    }
    dst[j]      = x1 * cs - x2 * sn;
    dst[j + 32] = x2 * cs + x1 * sn;
}

// ---------------- Flash attention (fp32, causal) ----------------
// grid: (32 q-tiles, 32 b*h). BQ=BK=64, d=128. 256 threads (16x16).
// Kt stored d-major with XOR swizzle on 4-float groups.
__device__ __forceinline__ int kt_idx(int d, int col) {
    return d * 64 + ((((col >> 2) ^ (d & 15)) << 2) | (col & 3));
}

__global__ void __launch_bounds__(256) flash_kernel(
    const float* __restrict__ Q, const float* __restrict__ Kp,
    const float* __restrict__ Vp, float* __restrict__ Y)
{
    extern __shared__ float sm[];
    float* Qs = sm;            // [64][128]
    float* Kt = sm + 8192;     // [128][64] swizzled
    float* Vs = sm + 16384;    // [64][128]
    float* Ps = sm + 24576;    // [64][68]

    const int bh = blockIdx.y;
    const int b  = bh >> 4;
    const int h  = bh & 15;
    const int qt = (int)gridDim.x - 1 - (int)blockIdx.x;  // heavy tiles first
    const int q0 = qt << 6;
    const int tid = threadIdx.x;
    const int tx = tid & 15;
    const int ty = tid >> 4;
    const float scale = 0.08838834764831845f;  // 1/sqrt(128)

    const float* Qg = Q + (size_t)(b * S_LEN + q0) * HDIM + h * HEADD;
#pragma unroll
    for (int i = 0; i < 8; i++) {
        int f4 = tid + (i << 8);
        int r  = f4 >> 5;
        int c4 = f4 & 31;
        *(float4*)&Qs[r * 128 + c4 * 4] = *(const float4*)&Qg[(size_t)r * HDIM + c4 * 4];
    }

    float o[4][8];
    float mrow[4], lrow[4];
#pragma unroll
    for (int i = 0; i < 4; i++) {
        mrow[i] = -1e30f; lrow[i] = 0.f;
#pragma unroll
        for (int j = 0; j < 8; j++) o[i][j] = 0.f;
    }

    const int nkv = qt + 1;
    for (int kt = 0; kt < nkv; kt++) {
        const int kv0 = kt << 6;
        __syncthreads();
        const float* Kg = Kp + (size_t)(b * S_LEN + kv0) * HDIM + h * HEADD;
        const float* Vg = Vp + (size_t)(b * S_LEN + kv0) * HDIM + h * HEADD;
#pragma unroll
        for (int i = 0; i < 8; i++) {
            int f4 = tid + (i << 8);
            int r  = f4 >> 5;
            int c4 = f4 & 31;
            float4 kv = *(const float4*)&Kg[(size_t)r * HDIM + c4 * 4];
            Kt[kt_idx(c4 * 4 + 0, r)] = kv.x;
            Kt[kt_idx(c4 * 4 + 1, r)] = kv.y;
            Kt[kt_idx(c4 * 4 + 2, r)] = kv.z;
            Kt[kt_idx(c4 * 4 + 3, r)] = kv.w;
            *(float4*)&Vs[r * 128 + c4 * 4] = *(const float4*)&Vg[(size_t)r * HDIM + c4 * 4];
        }
        __syncthreads();

        // S = Q K^T  (4x4 micro-tile)
        float acc[4][4];
#pragma unroll
        for (int i = 0; i < 4; i++)
#pragma unroll
            for (int c = 0; c < 4; c++) acc[i][c] = 0.f;

#pragma unroll 4
        for (int d = 0; d < 128; d += 4) {
            float qv[4][4], kc[4][4];
#pragma unroll
            for (int i = 0; i < 4; i++)
                *(float4*)qv[i] = *(float4*)&Qs[(ty * 4 + i) * 128 + d];
#pragma unroll
            for (int dd = 0; dd < 4; dd++)
                *(float4*)kc[dd] = *(float4*)&Kt[kt_idx(d + dd, tx * 4)];
#pragma unroll
            for (int i = 0; i < 4; i++)
#pragma unroll
                for (int dd = 0; dd < 4; dd++)
#pragma unroll
                    for (int c = 0; c < 4; c++)
                        acc[i][c] += qv[i][dd] * kc[dd][c];
        }

        const bool masked = (kt == nkv - 1);
#pragma unroll
        for (int i = 0; i < 4; i++) {
            int rg = q0 + ty * 4 + i;
            float tm = -1e30f;
#pragma unroll
            for (int c = 0; c < 4; c++) {
                float s = acc[i][c] * scale;
                if (masked) {
                    int cg = kv0 + tx * 4 + c;
                    if (cg > rg) s = -1e30f;
                }
                acc[i][c] = s;
                tm = fmaxf(tm, s);
            }
#pragma unroll
            for (int off = 1; off < 16; off <<= 1)
                tm = fmaxf(tm, __shfl_xor_sync(0xffffffffu, tm, off));
            float mnew = fmaxf(mrow[i], tm);
            float corr = expf(mrow[i] - mnew);
            float p[4];
            float ls = 0.f;
#pragma unroll
            for (int c = 0; c < 4; c++) {
                p[c] = expf(acc[i][c] - mnew);
                ls += p[c];
            }
            *(float4*)&Ps[(ty * 4 + i) * 68 + tx * 4] = *(float4*)p;
#pragma unroll
            for (int off = 1; off < 16; off <<= 1)
                ls += __shfl_xor_sync(0xffffffffu, ls, off);
            lrow[i] = lrow[i] * corr + ls;
            mrow[i] = mnew;
#pragma unroll
            for (int j = 0; j < 8; j++) o[i][j] *= corr;
        }
        __syncthreads();

        // O += P V  (4x8 micro-tile)
#pragma unroll 4
        for (int kc = 0; kc < 64; kc += 4) {
            float pv[4][4], vv[4][8];
#pragma unroll
            for (int i = 0; i < 4; i++)
                *(float4*)pv[i] = *(float4*)&Ps[(ty * 4 + i) * 68 + kc];
#pragma unroll
            for (int kk = 0; kk < 4; kk++) {
                *(float4*)&vv[kk][0] = *(float4*)&Vs[(kc + kk) * 128 + tx * 8];
                *(float4*)&vv[kk][4] = *(float4*)&Vs[(kc + kk) * 128 + tx * 8 + 4];
            }
#pragma unroll
            for (int i = 0; i < 4; i++)
#pragma unroll
                for (int kk = 0; kk < 4; kk++)
#pragma unroll
                    for (int j = 0; j < 8; j++)
                        o[i][j] += pv[i][kk] * vv[kk][j];
        }
    }

#pragma unroll
    for (int i = 0; i < 4; i++) {
        float inv = 1.0f / lrow[i];
        int rg = q0 + ty * 4 + i;
        float* dst = Y + (size_t)(b * S_LEN + rg) * HDIM + h * HEADD + tx * 8;
        float4 v0 = make_float4(o[i][0] * inv, o[i][1] * inv, o[i][2] * inv, o[i][3] * inv);
        float4 v1 = make_float4(o[i][4] * inv, o[i][5] * inv, o[i][6] * inv, o[i][7] * inv);
        *(float4*)dst = v0;
        *(float4*)(dst + 4) = v1;
    }
}

// ---------------- launch ----------------
extern "C" void kernel_launch(void* const* d_in, const int* in_sizes, int n_in,
                              void* d_out, int out_size)
{
    const float* hs   = (const float*)d_in[0];
    const float* Wkv  = (const float*)d_in[1];
    const float* Wq_d = (const float*)d_in[2];
    const float* Wk_u = (const float*)d_in[3];
    const float* Wq_u = (const float*)d_in[4];
    const float* Wv_u = (const float*)d_in[5];
    const float* Wrk  = (const float*)d_in[6];
    const float* Wrq  = (const float*)d_in[7];
    const float* Wo   = (const float*)d_in[8];
    float* out = (float*)d_out;

    float *p_wcat, *p_p1, *p_q, *p_k, *p_v, *p_qr, *p_y;
    cudaGetSymbolAddress((void**)&p_wcat, g_wcat);
    cudaGetSymbolAddress((void**)&p_p1, g_p1);
    cudaGetSymbolAddress((void**)&p_q, g_q);
    cudaGetSymbolAddress((void**)&p_k, g_k);
    cudaGetSymbolAddress((void**)&p_v, g_v);
    cudaGetSymbolAddress((void**)&p_qr, g_qr);
    cudaGetSymbolAddress((void**)&p_y, g_y);

    // 1. weight concat
    concat_w_kernel<<<(HDIM * 1536) / 256, 256>>>(Wkv, Wq_d, Wrk);

    // 2. fused down-projection: [4096,2048] @ [2048,1536] -> g_p1
    sgemm128_kernel<false><<<dim3(12, 32), 256>>>(hs, HDIM, p_wcat, 1536, p_p1, 1536, HDIM, 0);

    // 3. up-projections from latents (K=256)
    sgemm128_kernel<true ><<<dim3(8, 32), 256>>>(p_p1,        1536, Wk_u, 1024, p_k,  HDIM, 256, 0);   // k_c
    sgemm128_kernel<true ><<<dim3(8, 32), 256>>>(p_p1 + 256,  1536, Wq_u, 1024, p_q,  HDIM, 256, 0);   // q_c
    sgemm128_kernel<false><<<dim3(8, 32), 256>>>(p_p1 + 256,  1536, Wrq,  1024, p_qr, 1024, 256, 0);   // q_r raw
    sgemm128_kernel<false><<<dim3(16, 32), 256>>>(p_p1,       1536, Wv_u, 2048, p_v,  HDIM, 256, 0);   // v

    // 4. RoPE (q_r -> g_q, k_r -> g_k)
    rope_kernel<<<dim3((MROWS * NHEADS * 32) / 256, 2), 256>>>();

    // 5. causal flash attention
    const int smem_bytes = (64 * 128 + 128 * 64 + 64 * 128 + 64 * 68) * 4;  // 113 KB
    cudaFuncSetAttribute(flash_kernel, cudaFuncAttributeMaxDynamicSharedMemorySize, smem_bytes);
    flash_kernel<<<dim3(S_LEN / 64, BATCH * NHEADS), 256, smem_bytes>>>(p_q, p_k, p_v, p_y);

    // 6. output projection: [4096,2048] @ [2048,2048] -> out
    sgemm128_kernel<false><<<dim3(16, 32), 256>>>(p_y, HDIM, Wo, HDIM, out, HDIM, HDIM, 0);
}

// round 3
// speedup vs baseline: 3.2365x; 3.2365x over previous
#include <cuda_runtime.h>
#include <math.h>
#include <stdint.h>

#define S_LEN   2048
#define BATCH   2
#define HDIM    2048
#define NHEADS  16
#define HEADD   128
#define MROWS   (BATCH * S_LEN)   // 4096

// ---------------- scratch ----------------
__device__ float g_wcat[HDIM * 1536];     // [Wkv_d | Wq_d | Wrk]
__device__ float g_p1[MROWS * 1536];      // hs @ Wcat : [kv_d | q_d | k_r]
__device__ float g_q[MROWS * HDIM];       // q in [m][h*128+d] layout
__device__ float g_k[MROWS * HDIM];       // k in [m][h*128+d] layout
__device__ float g_v[MROWS * HDIM];       // v in [m][h*128+d] layout
__device__ float g_qr[MROWS * 1024];      // raw q_r before rope
__device__ float g_y[MROWS * HDIM];       // attention output

// ---------------- helpers ----------------
__device__ __forceinline__ float to_tf32(float x) {
    uint32_t u;
    asm("cvt.rna.tf32.f32 %0, %1;" : "=r"(u) : "f"(x));
    return __uint_as_float(u);
}

__device__ __forceinline__ void mma_tf32(float* c, const uint32_t* a, const uint32_t* b) {
    asm volatile(
        "mma.sync.aligned.m16n8k8.row.col.f32.tf32.tf32.f32 "
        "{%0,%1,%2,%3}, {%4,%5,%6,%7}, {%8,%9}, {%0,%1,%2,%3};\n"
        : "+f"(c[0]), "+f"(c[1]), "+f"(c[2]), "+f"(c[3])
        : "r"(a[0]), "r"(a[1]), "r"(a[2]), "r"(a[3]), "r"(b[0]), "r"(b[1]));
}

// ---------------- weight concat ----------------
__global__ void concat_w_kernel(const float* __restrict__ Wkv,
                                const float* __restrict__ Wq,
                                const float* __restrict__ Wrk) {
    int idx = blockIdx.x * blockDim.x + threadIdx.x;
    if (idx >= HDIM * 1536) return;
    int row = idx / 1536;
    int col = idx - row * 1536;
    float v;
    if (col < 256)      v = Wkv[row * 256 + col];
    else if (col < 512) v = Wq[row * 256 + (col - 256)];
    else                v = Wrk[row * 1024 + (col - 512)];
    g_wcat[idx] = v;
}

// ---------------- tf32 MMA GEMM: 128x128x16 tiles ----------------
// C[M,N] = A[M,K] @ B[K,N]; fp32 in/out, tf32 tensor-core accumulate in fp32.
// 256 threads = 8 warps as 2(m)x4(n); per warp 64x32 via 4x4 m16n8 tiles.
template<bool SPLIT>
__global__ void __launch_bounds__(256, 2) mma_gemm_kernel(
    const float* __restrict__ A, int lda,
    const float* __restrict__ B, int ldb,
    float* __restrict__ C, int ldc,
    int K, int coff)
{
    __shared__ float As[2][16][136];   // k-major A tile (tf32-rounded)
    __shared__ float Bs[2][16][136];   // k-major B tile

    const int tid  = threadIdx.x;
    const int lane = tid & 31;
    const int wid  = tid >> 5;
    const int wm   = (wid & 1) * 64;
    const int wn   = (wid >> 1) * 32;
    const int bm   = blockIdx.y * 128;
    const int bn   = blockIdx.x * 128;
    const int g    = lane >> 2;
    const int j    = lane & 3;

    float acc[4][4][4];
#pragma unroll
    for (int mt = 0; mt < 4; mt++)
#pragma unroll
        for (int nt = 0; nt < 4; nt++)
#pragma unroll
            for (int e = 0; e < 4; e++) acc[mt][nt][e] = 0.f;

    float4 ra[2], rb[2];

    // prologue: load tile 0
#pragma unroll
    for (int i = 0; i < 2; i++) {
        int f4 = tid + i * 256;
        ra[i] = *(const float4*)(A + (size_t)(bm + (f4 >> 2)) * lda + (f4 & 3) * 4);
        rb[i] = *(const float4*)(B + (size_t)(f4 >> 5) * ldb + bn + (f4 & 31) * 4);
    }
#pragma unroll
    for (int i = 0; i < 2; i++) {
        int f4 = tid + i * 256;
        int r = f4 >> 2, kq = f4 & 3;
        As[0][kq * 4 + 0][r] = to_tf32(ra[i].x);
        As[0][kq * 4 + 1][r] = to_tf32(ra[i].y);
        As[0][kq * 4 + 2][r] = to_tf32(ra[i].z);
        As[0][kq * 4 + 3][r] = to_tf32(ra[i].w);
        int rk = f4 >> 5, c4 = f4 & 31;
        float4 t = make_float4(to_tf32(rb[i].x), to_tf32(rb[i].y), to_tf32(rb[i].z), to_tf32(rb[i].w));
        *(float4*)&Bs[0][rk][c4 * 4] = t;
    }

    const int nIter = K >> 4;
    int buf = 0;
    for (int it = 0; it < nIter; it++) {
        __syncthreads();
        const bool more = (it + 1 < nIter);
        if (more) {
            int k0 = (it + 1) << 4;
#pragma unroll
            for (int i = 0; i < 2; i++) {
                int f4 = tid + i * 256;
                ra[i] = *(const float4*)(A + (size_t)(bm + (f4 >> 2)) * lda + k0 + (f4 & 3) * 4);
                rb[i] = *(const float4*)(B + (size_t)(k0 + (f4 >> 5)) * ldb + bn + (f4 & 31) * 4);
            }
        }
        // compute from smem[buf]
#pragma unroll
        for (int s = 0; s < 2; s++) {
            const int k = s * 8 + j;
            uint32_t af[4][4], bf[4][2];
#pragma unroll
            for (int mt = 0; mt < 4; mt++) {
                int r = wm + mt * 16 + g;
                af[mt][0] = __float_as_uint(As[buf][k][r]);
                af[mt][1] = __float_as_uint(As[buf][k][r + 8]);
                af[mt][2] = __float_as_uint(As[buf][k + 4][r]);
                af[mt][3] = __float_as_uint(As[buf][k + 4][r + 8]);
            }
#pragma unroll
            for (int nt = 0; nt < 4; nt++) {
                int c = wn + nt * 8 + g;
                bf[nt][0] = __float_as_uint(Bs[buf][k][c]);
                bf[nt][1] = __float_as_uint(Bs[buf][k + 4][c]);
            }
#pragma unroll
            for (int mt = 0; mt < 4; mt++)
#pragma unroll
                for (int nt = 0; nt < 4; nt++)
                    mma_tf32(acc[mt][nt], af[mt], bf[nt]);
        }
        if (more) {
            int nb = buf ^ 1;
#pragma unroll
            for (int i = 0; i < 2; i++) {
                int f4 = tid + i * 256;
                int r = f4 >> 2, kq = f4 & 3;
                As[nb][kq * 4 + 0][r] = to_tf32(ra[i].x);
                As[nb][kq * 4 + 1][r] = to_tf32(ra[i].y);
                As[nb][kq * 4 + 2][r] = to_tf32(ra[i].z);
                As[nb][kq * 4 + 3][r] = to_tf32(ra[i].w);
                int rk = f4 >> 5, c4 = f4 & 31;
                float4 t = make_float4(to_tf32(rb[i].x), to_tf32(rb[i].y), to_tf32(rb[i].z), to_tf32(rb[i].w));
                *(float4*)&Bs[nb][rk][c4 * 4] = t;
            }
        }
        buf ^= 1;
    }

    // epilogue
#pragma unroll
    for (int mt = 0; mt < 4; mt++) {
        int row = bm + wm + mt * 16 + g;
#pragma unroll
        for (int nt = 0; nt < 4; nt++) {
            int n = bn + wn + nt * 8 + j * 2;
            int col = SPLIT ? (((n >> 6) << 7) + (n & 63) + coff) : n;
            float2 v0 = make_float2(acc[mt][nt][0], acc[mt][nt][1]);
            float2 v1 = make_float2(acc[mt][nt][2], acc[mt][nt][3]);
            *(float2*)(C + (size_t)row * ldc + col) = v0;
            *(float2*)(C + (size_t)(row + 8) * ldc + col) = v1;
        }
    }
}

// ---------------- RoPE ----------------
__global__ void rope_kernel() {
    int idx = blockIdx.x * blockDim.x + threadIdx.x;  // over 4096*16*32
    int isK = blockIdx.y;
    int m   = idx >> 9;
    int rem = idx & 511;
    int h   = rem >> 5;
    int j   = rem & 31;
    int s   = m & (S_LEN - 1);

    float inv = powf(10000.0f, -(float)j * (1.0f / 32.0f));
    float ang = (float)s * inv;
    float sn, cs;
    sincosf(ang, &sn, &cs);

    float x1, x2;
    float* dst;
    if (isK) {
        const float* src = g_p1 + (size_t)m * 1536 + 512 + h * 64;
        x1 = src[j]; x2 = src[j + 32];
        dst = g_k + (size_t)m * HDIM + h * HEADD + 64;
    } else {
        const float* src = g_qr + (size_t)m * 1024 + h * 64;
        x1 = src[j]; x2 = src[j + 32];
        dst = g_q + (size_t)m * HDIM + h * HEADD + 64;
    }
    dst[j]      = x1 * cs - x2 * sn;
    dst[j + 32] = x2 * cs + x1 * sn;
}

// ---------------- Flash attention (tf32 MMA, causal) ----------------
// BQ=128, BK=64, d=128; 256 threads = 8 warps, each warp owns 16 q-rows.
// Q lives in registers as persistent A-fragments; K, V read in natural
// row-major layout as col-major B fragments; P staged via smem.
// Smem: Ks [64][132]=8448, Vs [64][136]=8704, Ps [128][68]=8704.
__global__ void __launch_bounds__(256, 1) flash_mma_kernel(
    const float* __restrict__ Q, const float* __restrict__ Kp,
    const float* __restrict__ Vp, float* __restrict__ Y)
{
    extern __shared__ float sm[];
    float* Ks = sm;            // [64][132]
    float* Vs = sm + 8448;     // [64][136]
    float* Ps = sm + 17152;    // [128][68]

    const int tid  = threadIdx.x;
    const int lane = tid & 31;
    const int w    = tid >> 5;
    const int g    = lane >> 2;
    const int j    = lane & 3;
    const int bh   = blockIdx.y;
    const int b    = bh >> 4;
    const int h    = bh & 15;
    const int qt   = (int)gridDim.x - 1 - (int)blockIdx.x;
    const int q0   = qt << 7;
    const float scale = 0.08838834764831845f;  // 1/sqrt(128)

    // ---- stage Q (128x128) into smem (aliased), extract persistent A frags
    const float* Qg = Q + (size_t)(b * S_LEN + q0) * HDIM + h * HEADD;
#pragma unroll
    for (int i = 0; i < 16; i++) {
        int f4 = tid + (i << 8);
        int r = f4 >> 5, c4 = f4 & 31;
        float4 v = *(const float4*)&Qg[(size_t)r * HDIM + c4 * 4];
        float4 t = make_float4(to_tf32(v.x), to_tf32(v.y), to_tf32(v.z), to_tf32(v.w));
        *(float4*)&sm[r * 132 + c4 * 4] = t;
    }
    __syncthreads();
    uint32_t qa[16][4];
    {
        const int r0 = w * 16 + g;
#pragma unroll
        for (int ks = 0; ks < 16; ks++) {
            int c = ks * 8 + j;
            qa[ks][0] = __float_as_uint(sm[r0 * 132 + c]);
            qa[ks][1] = __float_as_uint(sm[(r0 + 8) * 132 + c]);
            qa[ks][2] = __float_as_uint(sm[r0 * 132 + c + 4]);
            qa[ks][3] = __float_as_uint(sm[(r0 + 8) * 132 + c + 4]);
        }
    }

    float o[16][4];
#pragma unroll
    for (int nt = 0; nt < 16; nt++)
#pragma unroll
        for (int e = 0; e < 4; e++) o[nt][e] = 0.f;
    float m0 = -1e30f, m1 = -1e30f, l0 = 0.f, l1 = 0.f;

    const int nkv = 2 * qt + 2;
    for (int t = 0; t < nkv; t++) {
        const int kv0 = t << 6;
        __syncthreads();  // prev iter fully consumed smem (incl. Q stage at t=0)
        const float* Kg = Kp + (size_t)(b * S_LEN + kv0) * HDIM + h * HEADD;
        const float* Vg = Vp + (size_t)(b * S_LEN + kv0) * HDIM + h * HEADD;
#pragma unroll
        for (int i = 0; i < 8; i++) {
            int f4 = tid + (i << 8);
            int r = f4 >> 5, c4 = f4 & 31;
            float4 kv = *(const float4*)&Kg[(size_t)r * HDIM + c4 * 4];
            float4 tk = make_float4(to_tf32(kv.x), to_tf32(kv.y), to_tf32(kv.z), to_tf32(kv.w));
            *(float4*)&Ks[r * 132 + c4 * 4] = tk;
            float4 vv = *(const float4*)&Vg[(size_t)r * HDIM + c4 * 4];
            float4 tv = make_float4(to_tf32(vv.x), to_tf32(vv.y), to_tf32(vv.z), to_tf32(vv.w));
            *(float4*)&Vs[r * 136 + c4 * 4] = tv;
        }
        __syncthreads();

        // ---- S = Q K^T
        float s[8][4];
#pragma unroll
        for (int nt = 0; nt < 8; nt++)
#pragma unroll
            for (int e = 0; e < 4; e++) s[nt][e] = 0.f;
#pragma unroll
        for (int ks = 0; ks < 16; ks++) {
            const int kc = ks * 8 + j;
#pragma unroll
            for (int nt = 0; nt < 8; nt++) {
                uint32_t bf[2];
                bf[0] = __float_as_uint(Ks[(nt * 8 + g) * 132 + kc]);
                bf[1] = __float_as_uint(Ks[(nt * 8 + g) * 132 + kc + 4]);
                mma_tf32(s[nt], qa[ks], bf);
            }
        }

        // ---- online softmax
        const bool needm = (kv0 + 63 > q0);
        const int gr0 = q0 + w * 16 + g;
        const int gr1 = gr0 + 8;
        float tm0 = -1e30f, tm1 = -1e30f;
#pragma unroll
        for (int nt = 0; nt < 8; nt++) {
            int c0 = kv0 + nt * 8 + 2 * j;
#pragma unroll
            for (int e = 0; e < 2; e++) {
                float v0 = s[nt][e] * scale;
                float v1 = s[nt][2 + e] * scale;
                if (needm) {
                    if (c0 + e > gr0) v0 = -1e30f;
                    if (c0 + e > gr1) v1 = -1e30f;
                }
                s[nt][e] = v0; s[nt][2 + e] = v1;
                tm0 = fmaxf(tm0, v0); tm1 = fmaxf(tm1, v1);
            }
        }
        tm0 = fmaxf(tm0, __shfl_xor_sync(0xffffffffu, tm0, 1));
        tm0 = fmaxf(tm0, __shfl_xor_sync(0xffffffffu, tm0, 2));
        tm1 = fmaxf(tm1, __shfl_xor_sync(0xffffffffu, tm1, 1));
        tm1 = fmaxf(tm1, __shfl_xor_sync(0xffffffffu, tm1, 2));
        const float mn0 = fmaxf(m0, tm0), mn1 = fmaxf(m1, tm1);
        const float cr0 = __expf(m0 - mn0), cr1 = __expf(m1 - mn1);
        float sum0 = 0.f, sum1 = 0.f;
        const int pr0 = w * 16 + g;
#pragma unroll
        for (int nt = 0; nt < 8; nt++) {
            float p0 = __expf(s[nt][0] - mn0);
            float p1 = __expf(s[nt][1] - mn0);
            float p2 = __expf(s[nt][2] - mn1);
            float p3 = __expf(s[nt][3] - mn1);
            sum0 += p0 + p1; sum1 += p2 + p3;
            float2 w0 = make_float2(to_tf32(p0), to_tf32(p1));
            float2 w1 = make_float2(to_tf32(p2), to_tf32(p3));
            *(float2*)&Ps[pr0 * 68 + nt * 8 + 2 * j] = w0;
            *(float2*)&Ps[(pr0 + 8) * 68 + nt * 8 + 2 * j] = w1;
        }
        sum0 += __shfl_xor_sync(0xffffffffu, sum0, 1);
        sum0 += __shfl_xor_sync(0xffffffffu, sum0, 2);
        sum1 += __shfl_xor_sync(0xffffffffu, sum1, 1);
        sum1 += __shfl_xor_sync(0xffffffffu, sum1, 2);
        l0 = l0 * cr0 + sum0; l1 = l1 * cr1 + sum1;
        m0 = mn0; m1 = mn1;
#pragma unroll
        for (int nt = 0; nt < 16; nt++) {
            o[nt][0] *= cr0; o[nt][1] *= cr0;
            o[nt][2] *= cr1; o[nt][3] *= cr1;
        }
        __syncthreads();

        // ---- O += P V
#pragma unroll
        for (int kk = 0; kk < 8; kk++) {
            uint32_t pa[4];
            const int kc = kk * 8 + j;
            pa[0] = __float_as_uint(Ps[(w * 16 + g) * 68 + kc]);
            pa[1] = __float_as_uint(Ps[(w * 16 + g + 8) * 68 + kc]);
            pa[2] = __float_as_uint(Ps[(w * 16 + g) * 68 + kc + 4]);
            pa[3] = __float_as_uint(Ps[(w * 16 + g + 8) * 68 + kc + 4]);
#pragma unroll
            for (int nt = 0; nt < 16; nt++) {
                uint32_t bv[2];
                bv[0] = __float_as_uint(Vs[kc * 136 + nt * 8 + g]);
                bv[1] = __float_as_uint(Vs[(kc + 4) * 136 + nt * 8 + g]);
                mma_tf32(o[nt], pa, bv);
            }
        }
    }

    // ---- epilogue
    const float inv0 = 1.f / l0, inv1 = 1.f / l1;
    const int gr0 = q0 + w * 16 + g;
    float* Y0 = Y + (size_t)(b * S_LEN + gr0) * HDIM + h * HEADD;
    float* Y1 = Y + (size_t)(b * S_LEN + gr0 + 8) * HDIM + h * HEADD;
#pragma unroll
    for (int nt = 0; nt < 16; nt++) {
        int c = nt * 8 + 2 * j;
        *(float2*)&Y0[c] = make_float2(o[nt][0] * inv0, o[nt][1] * inv0);
        *(float2*)&Y1[c] = make_float2(o[nt][2] * inv1, o[nt][3] * inv1);
    }
}

// ---------------- launch ----------------
extern "C" void kernel_launch(void* const* d_in, const int* in_sizes, int n_in,
                              void* d_out, int out_size)
{
    const float* hs   = (const float*)d_in[0];
    const float* Wkv  = (const float*)d_in[1];
    const float* Wq_d = (const float*)d_in[2];
    const float* Wk_u = (const float*)d_in[3];
    const float* Wq_u = (const float*)d_in[4];
    const float* Wv_u = (const float*)d_in[5];
    const float* Wrk  = (const float*)d_in[6];
    const float* Wrq  = (const float*)d_in[7];
    const float* Wo   = (const float*)d_in[8];
    float* out = (float*)d_out;

    float *p_wcat, *p_p1, *p_q, *p_k, *p_v, *p_qr, *p_y;
    cudaGetSymbolAddress((void**)&p_wcat, g_wcat);
    cudaGetSymbolAddress((void**)&p_p1, g_p1);
    cudaGetSymbolAddress((void**)&p_q, g_q);
    cudaGetSymbolAddress((void**)&p_k, g_k);
    cudaGetSymbolAddress((void**)&p_v, g_v);
    cudaGetSymbolAddress((void**)&p_qr, g_qr);
    cudaGetSymbolAddress((void**)&p_y, g_y);

    // 1. weight concat
    concat_w_kernel<<<(HDIM * 1536) / 256, 256>>>(Wkv, Wq_d, Wrk);

    // 2. fused down-projection: [4096,2048] @ [2048,1536]
    mma_gemm_kernel<false><<<dim3(12, 32), 256>>>(hs, HDIM, p_wcat, 1536, p_p1, 1536, HDIM, 0);

    // 3. up-projections from latents (K=256)
    mma_gemm_kernel<true ><<<dim3(8, 32), 256>>>(p_p1,       1536, Wk_u, 1024, p_k,  HDIM, 256, 0);   // k_c
    mma_gemm_kernel<true ><<<dim3(8, 32), 256>>>(p_p1 + 256, 1536, Wq_u, 1024, p_q,  HDIM, 256, 0);   // q_c
    mma_gemm_kernel<false><<<dim3(8, 32), 256>>>(p_p1 + 256, 1536, Wrq,  1024, p_qr, 1024, 256, 0);   // q_r raw
    mma_gemm_kernel<false><<<dim3(16, 32), 256>>>(p_p1,      1536, Wv_u, 2048, p_v,  HDIM, 256, 0);   // v

    // 4. RoPE
    rope_kernel<<<dim3((MROWS * NHEADS * 32) / 256, 2), 256>>>();

    // 5. causal flash attention (tf32 MMA)
    const int smem_bytes = (8448 + 8704 + 8704) * 4;  // 103424 B
    cudaFuncSetAttribute(flash_mma_kernel, cudaFuncAttributeMaxDynamicSharedMemorySize, smem_bytes);
    flash_mma_kernel<<<dim3(S_LEN / 128, BATCH * NHEADS), 256, smem_bytes>>>(p_q, p_k, p_v, p_y);

    // 6. output projection: [4096,2048] @ [2048,2048]
    mma_gemm_kernel<false><<<dim3(16, 32), 256>>>(p_y, HDIM, Wo, HDIM, out, HDIM, HDIM, 0);
}

// round 5
// speedup vs baseline: 3.7227x; 1.1502x over previous
#include <cuda_runtime.h>
#include <math.h>
#include <stdint.h>

#define S_LEN   2048
#define BATCH   2
#define HDIM    2048
#define NHEADS  16
#define HEADD   128
#define MROWS   (BATCH * S_LEN)   // 4096

// ---------------- scratch ----------------
__device__ float g_wcat[HDIM * 1536];     // [Wkv_d | Wq_d | Wrk] (tf32-rounded)
__device__ float g_hs[MROWS * HDIM];      // tf32-rounded hidden states
__device__ float g_wr[5505024];           // rounded: Wk_u|Wq_u|Wrq|Wv_u|Wo
__device__ float g_p1[MROWS * 1536];      // hs @ Wcat : [kv_d | q_d | k_r]
__device__ float g_q[MROWS * HDIM];       // q in [m][h*128+d] layout
__device__ float g_k[MROWS * HDIM];       // k
__device__ float g_v[MROWS * HDIM];       // v
__device__ float g_qr[MROWS * 1024];      // raw q_r before rope
__device__ float g_y[MROWS * HDIM];       // attention output

#define WKU_OFF 0
#define WQU_OFF 262144
#define WRQ_OFF 524288
#define WVU_OFF 786432
#define WO_OFF  1310720

// ---------------- helpers ----------------
__device__ __forceinline__ float to_tf32(float x) {
    uint32_t u;
    asm("cvt.rna.tf32.f32 %0, %1;" : "=r"(u) : "f"(x));
    return __uint_as_float(u);
}

__device__ __forceinline__ void mma_tf32(float* c, const uint32_t* a, const uint32_t* b) {
    asm volatile(
        "mma.sync.aligned.m16n8k8.row.col.f32.tf32.tf32.f32 "
        "{%0,%1,%2,%3}, {%4,%5,%6,%7}, {%8,%9}, {%0,%1,%2,%3};\n"
        : "+f"(c[0]), "+f"(c[1]), "+f"(c[2]), "+f"(c[3])
        : "r"(a[0]), "r"(a[1]), "r"(a[2]), "r"(a[3]), "r"(b[0]), "r"(b[1]));
}

__device__ __forceinline__ uint32_t smem_u32(const void* p) {
    uint32_t a;
    asm("{ .reg .u64 t; cvta.to.shared.u64 t, %1; cvt.u32.u64 %0, t; }" : "=r"(a) : "l"(p));
    return a;
}

__device__ __forceinline__ void cp16(uint32_t dst, const void* src) {
    asm volatile("cp.async.cg.shared.global [%0], [%1], 16;" :: "r"(dst), "l"(src));
}
__device__ __forceinline__ void cp_commit() {
    asm volatile("cp.async.commit_group;" ::: "memory");
}
template<int N>
__device__ __forceinline__ void cp_wait() {
    asm volatile("cp.async.wait_group %0;" :: "n"(N) : "memory");
}

// ---------------- rounding / concat ----------------
__global__ void round_kernel(const float* __restrict__ src, float* __restrict__ dst, int n) {
    int i = (blockIdx.x * blockDim.x + threadIdx.x) * 4;
    if (i >= n) return;
    float4 v = *(const float4*)(src + i);
    v.x = to_tf32(v.x); v.y = to_tf32(v.y); v.z = to_tf32(v.z); v.w = to_tf32(v.w);
    *(float4*)(dst + i) = v;
}

__global__ void concat_w_kernel(const float* __restrict__ Wkv,
                                const float* __restrict__ Wq,
                                const float* __restrict__ Wrk) {
    int idx = blockIdx.x * blockDim.x + threadIdx.x;
    if (idx >= HDIM * 1536) return;
    int row = idx / 1536;
    int col = idx - row * 1536;
    float v;
    if (col < 256)      v = Wkv[row * 256 + col];
    else if (col < 512) v = Wq[row * 256 + (col - 256)];
    else                v = Wrk[row * 1024 + (col - 512)];
    g_wcat[idx] = to_tf32(v);
}

// ---------------- tf32 GEMM: 128x128 tile, 3-stage cp.async ----------------
// Inputs MUST be pre-rounded to tf32. A row-major [M,K] copied to As[m][k]
// stride 36; B row-major [K,N] copied to Bs[k][n] stride 136.
// 256 thr = 8 warps (2m x 4n), warp tile 64x32, 4x4 m16n8k8 per k8 step.
#define AST 36
#define BST 136
#define STAGE_F (128 * AST + 32 * BST)   // floats per stage: 4608+4352=8960
#define GEMM_SMEM (3 * STAGE_F * 4)      // 107520 B

template<bool SPLIT, bool ROUND>
__global__ void __launch_bounds__(256, 2) tf32_gemm_kernel(
    const float* __restrict__ A, int lda,
    const float* __restrict__ B, int ldb,
    float* __restrict__ C, int ldc,
    int K, int coff)
{
    extern __shared__ float smem[];
    const uint32_t sb = smem_u32(smem);
    const int tid  = threadIdx.x;
    const int lane = tid & 31;
    const int wid  = tid >> 5;
    const int wm   = (wid & 1) * 64;
    const int wn   = (wid >> 1) * 32;
    const int bm   = blockIdx.y * 128;
    const int bn   = blockIdx.x * 128;
    const int g    = lane >> 2;
    const int j    = lane & 3;

    float acc[4][4][4];
#pragma unroll
    for (int mt = 0; mt < 4; mt++)
#pragma unroll
        for (int nt = 0; nt < 4; nt++)
#pragma unroll
            for (int e = 0; e < 4; e++) acc[mt][nt][e] = 0.f;

    const int nstage = K >> 5;

    // precomputed per-thread copy coords
    const int ar  = tid >> 1;            // rows 0..127, 2 threads/row
    const int ac  = (tid & 1) * 4;       // float4 col 0 or 4 (x2 below)
    const int brk = tid >> 5;            // 8 k-rows per 256thr pass (x4 below)
    const int bc4 = tid & 31;

    auto issue = [&](int it) {
        const int k0 = it << 5;
        const uint32_t abase = sb + ((it % 3) * STAGE_F) * 4;
        const uint32_t bbase = abase + 128 * AST * 4;
        // A: 128x32 floats = 1024 float4; thread does 2 (row ar, cols ac, ac+... )
#pragma unroll
        for (int i = 0; i < 2; i++) {
            int c4 = ac + i * 2;  // wait: need cols {0,4} pattern per i
            c4 = (tid & 1) * 4 + i * 2;
            (void)c4;
        }
        // simpler: f4 indexing
#pragma unroll
        for (int i = 0; i < 4; i++) {
            int f4 = tid + (i << 8);
            int r = f4 >> 3, c4 = f4 & 7;
            cp16(abase + (uint32_t)(r * AST + c4 * 4) * 4,
                 A + (size_t)(bm + r) * lda + k0 + c4 * 4);
        }
        // B: 32x128 floats = 1024 float4
#pragma unroll
        for (int i = 0; i < 4; i++) {
            int f4 = tid + (i << 8);
            int rk = f4 >> 5, c4 = f4 & 31;
            cp16(bbase + (uint32_t)(rk * BST + c4 * 4) * 4,
                 B + (size_t)(k0 + rk) * ldb + bn + c4 * 4);
        }
        cp_commit();
    };
    (void)ar; (void)ac; (void)brk; (void)bc4;

    issue(0);
    if (nstage > 1) issue(1);

    for (int it = 0; it < nstage; it++) {
        if (it + 2 < nstage) issue(it + 2);
        else cp_commit();  // empty group keeps the count aligned
        cp_wait<2>();
        __syncthreads();

        const float* As = smem + (it % 3) * STAGE_F;
        const float* Bs = As + 128 * AST;
#pragma unroll
        for (int s = 0; s < 4; s++) {
            const int k = s * 8 + j;
            uint32_t af[4][4], bf[4][2];
#pragma unroll
            for (int mt = 0; mt < 4; mt++) {
                const int r = wm + mt * 16 + g;
                af[mt][0] = __float_as_uint(As[r * AST + k]);
                af[mt][1] = __float_as_uint(As[(r + 8) * AST + k]);
                af[mt][2] = __float_as_uint(As[r * AST + k + 4]);
                af[mt][3] = __float_as_uint(As[(r + 8) * AST + k + 4]);
            }
#pragma unroll
            for (int nt = 0; nt < 4; nt++) {
                const int c = wn + nt * 8 + g;
                bf[nt][0] = __float_as_uint(Bs[k * BST + c]);
                bf[nt][1] = __float_as_uint(Bs[(k + 4) * BST + c]);
            }
#pragma unroll
            for (int mt = 0; mt < 4; mt++)
#pragma unroll
                for (int nt = 0; nt < 4; nt++)
                    mma_tf32(acc[mt][nt], af[mt], bf[nt]);
        }
        __syncthreads();
    }

    // epilogue
#pragma unroll
    for (int mt = 0; mt < 4; mt++) {
        int row = bm + wm + mt * 16 + g;
#pragma unroll
        for (int nt = 0; nt < 4; nt++) {
            int n = bn + wn + nt * 8 + j * 2;
            int col = SPLIT ? (((n >> 6) << 7) + (n & 63) + coff) : n;
            float2 v0, v1;
            if (ROUND) {
                v0 = make_float2(to_tf32(acc[mt][nt][0]), to_tf32(acc[mt][nt][1]));
                v1 = make_float2(to_tf32(acc[mt][nt][2]), to_tf32(acc[mt][nt][3]));
            } else {
                v0 = make_float2(acc[mt][nt][0], acc[mt][nt][1]);
                v1 = make_float2(acc[mt][nt][2], acc[mt][nt][3]);
            }
            *(float2*)(C + (size_t)row * ldc + col) = v0;
            *(float2*)(C + (size_t)(row + 8) * ldc + col) = v1;
        }
    }
}

// ---------------- RoPE (outputs tf32-rounded) ----------------
__global__ void rope_kernel() {
    int idx = blockIdx.x * blockDim.x + threadIdx.x;  // over 4096*16*32
    int isK = blockIdx.y;
    int m   = idx >> 9;
    int rem = idx & 511;
    int h   = rem >> 5;
    int j   = rem & 31;
    int s   = m & (S_LEN - 1);

    float inv = powf(10000.0f, -(float)j * (1.0f / 32.0f));
    float ang = (float)s * inv;
    float sn, cs;
    sincosf(ang, &sn, &cs);

    float x1, x2;
    float* dst;
    if (isK) {
        const float* src = g_p1 + (size_t)m * 1536 + 512 + h * 64;
        x1 = src[j]; x2 = src[j + 32];
        dst = g_k + (size_t)m * HDIM + h * HEADD + 64;
    } else {
        const float* src = g_qr + (size_t)m * 1024 + h * 64;
        x1 = src[j]; x2 = src[j + 32];
        dst = g_q + (size_t)m * HDIM + h * HEADD + 64;
    }
    dst[j]      = to_tf32(x1 * cs - x2 * sn);
    dst[j + 32] = to_tf32(x2 * cs + x1 * sn);
}

// ---------------- Flash attention (tf32 mma.sync, causal, cp.async K/V) ----
// BQ=128, BK=64, d=128; 256 threads = 8 warps, each warp owns 16 q-rows.
// Smem floats: Ks[2][64*132], Vs[2][64*136], Ps[128*68] -> 43008 f = 172032 B.
#define KS_F 8448
#define VS_F 8704
#define KS0  0
#define KS1  KS_F
#define VS0  (2 * KS_F)
#define VS1  (2 * KS_F + VS_F)
#define PS0  (2 * KS_F + 2 * VS_F)
#define FLASH_SMEM ((2 * KS_F + 2 * VS_F + 8704) * 4)

__global__ void __launch_bounds__(256, 1) flash_mma_kernel(
    const float* __restrict__ Q, const float* __restrict__ Kp,
    const float* __restrict__ Vp, float* __restrict__ Y)
{
    extern __shared__ float sm[];
    const uint32_t sb = smem_u32(sm);
    float* Ps = sm + PS0;

    const int tid  = threadIdx.x;
    const int lane = tid & 31;
    const int w    = tid >> 5;
    const int g    = lane >> 2;
    const int j    = lane & 3;
    const int bh   = blockIdx.y;
    const int b    = bh >> 4;
    const int h    = bh & 15;
    const int qt   = (int)gridDim.x - 1 - (int)blockIdx.x;
    const int q0   = qt << 7;
    const float scale = 0.08838834764831845f;  // 1/sqrt(128)

    const float* Kbase = Kp + (size_t)b * S_LEN * HDIM + h * HEADD;
    const float* Vbase = Vp + (size_t)b * S_LEN * HDIM + h * HEADD;

    // ---- stage Q (128x128, pre-rounded) into smem (aliases Ks0/Ks1)
    const float* Qg = Q + (size_t)(b * S_LEN + q0) * HDIM + h * HEADD;
#pragma unroll
    for (int i = 0; i < 16; i++) {
        int f4 = tid + (i << 8);
        int r = f4 >> 5, c4 = f4 & 31;
        *(float4*)&sm[r * 132 + c4 * 4] = *(const float4*)&Qg[(size_t)r * HDIM + c4 * 4];
    }
    __syncthreads();
    uint32_t qa[16][4];
    {
        const int r0 = w * 16 + g;
#pragma unroll
        for (int ks = 0; ks < 16; ks++) {
            int c = ks * 8 + j;
            qa[ks][0] = __float_as_uint(sm[r0 * 132 + c]);
            qa[ks][1] = __float_as_uint(sm[(r0 + 8) * 132 + c]);
            qa[ks][2] = __float_as_uint(sm[r0 * 132 + c + 4]);
            qa[ks][3] = __float_as_uint(sm[(r0 + 8) * 132 + c + 4]);
        }
    }
    __syncthreads();

    auto issue_kv = [&](int t) {
        const int d = t & 1;
        const float* Kg = Kbase + (size_t)(t << 6) * HDIM;
        const float* Vg = Vbase + (size_t)(t << 6) * HDIM;
        const uint32_t kb = sb + (d ? KS1 : KS0) * 4;
        const uint32_t vb = sb + (d ? VS1 : VS0) * 4;
#pragma unroll
        for (int i = 0; i < 8; i++) {
            int f4 = tid + (i << 8);
            int r = f4 >> 5, c4 = f4 & 31;
            cp16(kb + (uint32_t)(r * 132 + c4 * 4) * 4, Kg + (size_t)r * HDIM + c4 * 4);
            cp16(vb + (uint32_t)(r * 136 + c4 * 4) * 4, Vg + (size_t)r * HDIM + c4 * 4);
        }
        cp_commit();
    };

    float o[16][4];
#pragma unroll
    for (int nt = 0; nt < 16; nt++)
#pragma unroll
        for (int e = 0; e < 4; e++) o[nt][e] = 0.f;
    float m0 = -1e30f, m1 = -1e30f, l0 = 0.f, l1 = 0.f;

    const int nkv = 2 * qt + 2;
    issue_kv(0);

    for (int t = 0; t < nkv; t++) {
        const int kv0 = t << 6;
        if (t + 1 < nkv) issue_kv(t + 1);
        else cp_commit();
        cp_wait<1>();
        __syncthreads();

        const float* Ks = sm + ((t & 1) ? KS1 : KS0);
        const float* Vs = sm + ((t & 1) ? VS1 : VS0);

        // ---- S = Q K^T
        float s[8][4];
#pragma unroll
        for (int nt = 0; nt < 8; nt++)
#pragma unroll
            for (int e = 0; e < 4; e++) s[nt][e] = 0.f;
#pragma unroll
        for (int ks = 0; ks < 16; ks++) {
            const int kc = ks * 8 + j;
#pragma unroll
            for (int nt = 0; nt < 8; nt++) {
                uint32_t bf[2];
                bf[0] = __float_as_uint(Ks[(nt * 8 + g) * 132 + kc]);
                bf[1] = __float_as_uint(Ks[(nt * 8 + g) * 132 + kc + 4]);
                mma_tf32(s[nt], qa[ks], bf);
            }
        }

        // ---- online softmax
        const bool needm = (kv0 + 63 > q0);
        const int gr0 = q0 + w * 16 + g;
        const int gr1 = gr0 + 8;
        float tm0 = -1e30f, tm1 = -1e30f;
#pragma unroll
        for (int nt = 0; nt < 8; nt++) {
            int c0 = kv0 + nt * 8 + 2 * j;
#pragma unroll
            for (int e = 0; e < 2; e++) {
                float v0 = s[nt][e] * scale;
                float v1 = s[nt][2 + e] * scale;
                if (needm) {
                    if (c0 + e > gr0) v0 = -1e30f;
                    if (c0 + e > gr1) v1 = -1e30f;
                }
                s[nt][e] = v0; s[nt][2 + e] = v1;
                tm0 = fmaxf(tm0, v0); tm1 = fmaxf(tm1, v1);
            }
        }
        tm0 = fmaxf(tm0, __shfl_xor_sync(0xffffffffu, tm0, 1));
        tm0 = fmaxf(tm0, __shfl_xor_sync(0xffffffffu, tm0, 2));
        tm1 = fmaxf(tm1, __shfl_xor_sync(0xffffffffu, tm1, 1));
        tm1 = fmaxf(tm1, __shfl_xor_sync(0xffffffffu, tm1, 2));
        const float mn0 = fmaxf(m0, tm0), mn1 = fmaxf(m1, tm1);
        const float cr0 = __expf(m0 - mn0), cr1 = __expf(m1 - mn1);
        float sum0 = 0.f, sum1 = 0.f;
        const int pr0 = w * 16 + g;
#pragma unroll
        for (int nt = 0; nt < 8; nt++) {
            float p0 = __expf(s[nt][0] - mn0);
            float p1 = __expf(s[nt][1] - mn0);
            float p2 = __expf(s[nt][2] - mn1);
            float p3 = __expf(s[nt][3] - mn1);
            sum0 += p0 + p1; sum1 += p2 + p3;
            float2 w0 = make_float2(to_tf32(p0), to_tf32(p1));
            float2 w1 = make_float2(to_tf32(p2), to_tf32(p3));
            *(float2*)&Ps[pr0 * 68 + nt * 8 + 2 * j] = w0;
            *(float2*)&Ps[(pr0 + 8) * 68 + nt * 8 + 2 * j] = w1;
        }
        sum0 += __shfl_xor_sync(0xffffffffu, sum0, 1);
        sum0 += __shfl_xor_sync(0xffffffffu, sum0, 2);
        sum1 += __shfl_xor_sync(0xffffffffu, sum1, 1);
        sum1 += __shfl_xor_sync(0xffffffffu, sum1, 2);
        l0 = l0 * cr0 + sum0; l1 = l1 * cr1 + sum1;
        m0 = mn0; m1 = mn1;
#pragma unroll
        for (int nt = 0; nt < 16; nt++) {
            o[nt][0] *= cr0; o[nt][1] *= cr0;
            o[nt][2] *= cr1; o[nt][3] *= cr1;
        }
        __syncthreads();

        // ---- O += P V
#pragma unroll
        for (int kk = 0; kk < 8; kk++) {
            uint32_t pa[4];
            const int kc = kk * 8 + j;
            pa[0] = __float_as_uint(Ps[(w * 16 + g) * 68 + kc]);
            pa[1] = __float_as_uint(Ps[(w * 16 + g + 8) * 68 + kc]);
            pa[2] = __float_as_uint(Ps[(w * 16 + g) * 68 + kc + 4]);
            pa[3] = __float_as_uint(Ps[(w * 16 + g + 8) * 68 + kc + 4]);
#pragma unroll
            for (int nt = 0; nt < 16; nt++) {
                uint32_t bv[2];
                bv[0] = __float_as_uint(Vs[kc * 136 + nt * 8 + g]);
                bv[1] = __float_as_uint(Vs[(kc + 4) * 136 + nt * 8 + g]);
                mma_tf32(o[nt], pa, bv);
            }
        }
        __syncthreads();
    }

    // ---- epilogue (round for the Wo GEMM's cp.async path)
    const float inv0 = 1.f / l0, inv1 = 1.f / l1;
    const int gr0 = q0 + w * 16 + g;
    float* Y0 = Y + (size_t)(b * S_LEN + gr0) * HDIM + h * HEADD;
    float* Y1 = Y + (size_t)(b * S_LEN + gr0 + 8) * HDIM + h * HEADD;
#pragma unroll
    for (int nt = 0; nt < 16; nt++) {
        int c = nt * 8 + 2 * j;
        *(float2*)&Y0[c] = make_float2(to_tf32(o[nt][0] * inv0), to_tf32(o[nt][1] * inv0));
        *(float2*)&Y1[c] = make_float2(to_tf32(o[nt][2] * inv1), to_tf32(o[nt][3] * inv1));
    }
}

// ---------------- launch ----------------
extern "C" void kernel_launch(void* const* d_in, const int* in_sizes, int n_in,
                              void* d_out, int out_size)
{
    const float* hs   = (const float*)d_in[0];
    const float* Wkv  = (const float*)d_in[1];
    const float* Wq_d = (const float*)d_in[2];
    const float* Wk_u = (const float*)d_in[3];
    const float* Wq_u = (const float*)d_in[4];
    const float* Wv_u = (const float*)d_in[5];
    const float* Wrk  = (const float*)d_in[6];
    const float* Wrq  = (const float*)d_in[7];
    const float* Wo   = (const float*)d_in[8];
    float* out = (float*)d_out;

    float *p_wcat, *p_hs, *p_wr, *p_p1, *p_q, *p_k, *p_v, *p_qr, *p_y;
    cudaGetSymbolAddress((void**)&p_wcat, g_wcat);
    cudaGetSymbolAddress((void**)&p_hs, g_hs);
    cudaGetSymbolAddress((void**)&p_wr, g_wr);
    cudaGetSymbolAddress((void**)&p_p1, g_p1);
    cudaGetSymbolAddress((void**)&p_q, g_q);
    cudaGetSymbolAddress((void**)&p_k, g_k);
    cudaGetSymbolAddress((void**)&p_v, g_v);
    cudaGetSymbolAddress((void**)&p_qr, g_qr);
    cudaGetSymbolAddress((void**)&p_y, g_y);

    cudaFuncSetAttribute(tf32_gemm_kernel<false, true>,
                         cudaFuncAttributeMaxDynamicSharedMemorySize, GEMM_SMEM);
    cudaFuncSetAttribute(tf32_gemm_kernel<true, true>,
                         cudaFuncAttributeMaxDynamicSharedMemorySize, GEMM_SMEM);
    cudaFuncSetAttribute(tf32_gemm_kernel<false, false>,
                         cudaFuncAttributeMaxDynamicSharedMemorySize, GEMM_SMEM);
    cudaFuncSetAttribute(flash_mma_kernel,
                         cudaFuncAttributeMaxDynamicSharedMemorySize, FLASH_SMEM);

    // 0. tf32 pre-rounding of all raw inputs
    concat_w_kernel<<<(HDIM * 1536) / 256, 256>>>(Wkv, Wq_d, Wrk);
    round_kernel<<<(MROWS * HDIM / 4 + 255) / 256, 256>>>(hs, p_hs, MROWS * HDIM);
    round_kernel<<<(262144 / 4 + 255) / 256, 256>>>(Wk_u, p_wr + WKU_OFF, 262144);
    round_kernel<<<(262144 / 4 + 255) / 256, 256>>>(Wq_u, p_wr + WQU_OFF, 262144);
    round_kernel<<<(262144 / 4 + 255) / 256, 256>>>(Wrq, p_wr + WRQ_OFF, 262144);
    round_kernel<<<(524288 / 4 + 255) / 256, 256>>>(Wv_u, p_wr + WVU_OFF, 524288);
    round_kernel<<<(4194304 / 4 + 255) / 256, 256>>>(Wo, p_wr + WO_OFF, 4194304);

    // 1. fused down-projection: [4096,2048] @ [2048,1536] (epilogue rounds)
    tf32_gemm_kernel<false, true><<<dim3(12, 32), 256, GEMM_SMEM>>>(
        p_hs, HDIM, p_wcat, 1536, p_p1, 1536, HDIM, 0);

    // 2. up-projections from latents (K=256)
    tf32_gemm_kernel<true,  true><<<dim3(8, 32), 256, GEMM_SMEM>>>(
        p_p1,       1536, p_wr + WKU_OFF, 1024, p_k,  HDIM, 256, 0);   // k_c
    tf32_gemm_kernel<true,  true><<<dim3(8, 32), 256, GEMM_SMEM>>>(
        p_p1 + 256, 1536, p_wr + WQU_OFF, 1024, p_q,  HDIM, 256, 0);   // q_c
    tf32_gemm_kernel<false, true><<<dim3(8, 32), 256, GEMM_SMEM>>>(
        p_p1 + 256, 1536, p_wr + WRQ_OFF, 1024, p_qr, 1024, 256, 0);   // q_r raw
    tf32_gemm_kernel<false, true><<<dim3(16, 32), 256, GEMM_SMEM>>>(
        p_p1,       1536, p_wr + WVU_OFF, 2048, p_v,  HDIM, 256, 0);   // v

    // 3. RoPE (rounds outputs)
    rope_kernel<<<dim3((MROWS * NHEADS * 32) / 256, 2), 256>>>();

    // 4. causal flash attention (tf32 mma.sync, cp.async K/V prefetch)
    flash_mma_kernel<<<dim3(S_LEN / 128, BATCH * NHEADS), 256, FLASH_SMEM>>>(
        p_q, p_k, p_v, p_y);

    // 5. output projection: [4096,2048] @ [2048,2048]
    tf32_gemm_kernel<false, false><<<dim3(16, 32), 256, GEMM_SMEM>>>(
        p_y, HDIM, p_wr + WO_OFF, HDIM, out, HDIM, HDIM, 0);
}

// round 6
// speedup vs baseline: 3.8344x; 1.0300x over previous
#include <cuda_runtime.h>
#include <math.h>
#include <stdint.h>

#define S_LEN   2048
#define BATCH   2
#define HDIM    2048
#define NHEADS  16
#define HEADD   128
#define MROWS   (BATCH * S_LEN)   // 4096

// ---------------- scratch ----------------
__device__ float g_wcat[HDIM * 1536];     // [Wkv_d | Wq_d | Wrk] (tf32-rounded)
__device__ float g_hs[MROWS * HDIM];      // tf32-rounded hidden states
__device__ float g_wr[5505024];           // rounded: Wk_u|Wq_u|Wrq|Wv_u|Wo
__device__ float g_p1[MROWS * 1536];      // hs @ Wcat : [kv_d | q_d | k_r]
__device__ float g_q[MROWS * HDIM];       // q in [m][h*128+d] layout
__device__ float g_k[MROWS * HDIM];       // k
__device__ float g_v[MROWS * HDIM];       // v
__device__ float g_qr[MROWS * 1024];      // raw q_r before rope
__device__ float g_y[MROWS * HDIM];       // attention output

#define WKU_OFF 0
#define WQU_OFF 262144
#define WRQ_OFF 524288
#define WVU_OFF 786432
#define WO_OFF  1310720

// ---------------- helpers ----------------
__device__ __forceinline__ float to_tf32(float x) {
    uint32_t u;
    asm("cvt.rna.tf32.f32 %0, %1;" : "=r"(u) : "f"(x));
    return __uint_as_float(u);
}

__device__ __forceinline__ void mma_tf32(float* c, const uint32_t* a, const uint32_t* b) {
    asm volatile(
        "mma.sync.aligned.m16n8k8.row.col.f32.tf32.tf32.f32 "
        "{%0,%1,%2,%3}, {%4,%5,%6,%7}, {%8,%9}, {%0,%1,%2,%3};\n"
        : "+f"(c[0]), "+f"(c[1]), "+f"(c[2]), "+f"(c[3])
        : "r"(a[0]), "r"(a[1]), "r"(a[2]), "r"(a[3]), "r"(b[0]), "r"(b[1]));
}

__device__ __forceinline__ uint32_t smem_u32(const void* p) {
    uint32_t a;
    asm("{ .reg .u64 t; cvta.to.shared.u64 t, %1; cvt.u32.u64 %0, t; }" : "=r"(a) : "l"(p));
    return a;
}

__device__ __forceinline__ void cp16(uint32_t dst, const void* src) {
    asm volatile("cp.async.cg.shared.global [%0], [%1], 16;" :: "r"(dst), "l"(src));
}
__device__ __forceinline__ void cp_commit() {
    asm volatile("cp.async.commit_group;" ::: "memory");
}
template<int N>
__device__ __forceinline__ void cp_wait() {
    asm volatile("cp.async.wait_group %0;" :: "n"(N) : "memory");
}

// ---------------- fused rounding (hs + 5 weights) ----------------
// float4-unit segment boundaries (cumulative):
//   hs   [0,       2097152)  -> g_hs
//   Wk_u [2097152, 2162688)
//   Wq_u [2162688, 2228224)
//   Wrq  [2228224, 2293760)
//   Wv_u [2293760, 2424832)
//   Wo   [2424832, 3473408)  weights -> g_wr + (i4-2097152)*4
__global__ void round_all_kernel(const float* __restrict__ hs,
                                 const float* __restrict__ wku,
                                 const float* __restrict__ wqu,
                                 const float* __restrict__ wrq,
                                 const float* __restrict__ wvu,
                                 const float* __restrict__ wo,
                                 float* __restrict__ dhs,
                                 float* __restrict__ dwr) {
    int i4 = blockIdx.x * blockDim.x + threadIdx.x;
    if (i4 >= 3473408) return;
    const float* src;
    float* dst;
    if (i4 < 2097152) {
        src = hs + (size_t)i4 * 4;
        dst = dhs + (size_t)i4 * 4;
    } else {
        int w4 = i4 - 2097152;
        dst = dwr + (size_t)w4 * 4;
        if (w4 < 65536)        src = wku + (size_t)w4 * 4;
        else if (w4 < 131072)  src = wqu + (size_t)(w4 - 65536) * 4;
        else if (w4 < 196608)  src = wrq + (size_t)(w4 - 131072) * 4;
        else if (w4 < 327680)  src = wvu + (size_t)(w4 - 196608) * 4;
        else                   src = wo  + (size_t)(w4 - 327680) * 4;
    }
    float4 v = *(const float4*)src;
    v.x = to_tf32(v.x); v.y = to_tf32(v.y); v.z = to_tf32(v.z); v.w = to_tf32(v.w);
    *(float4*)dst = v;
}

__global__ void concat_w_kernel(const float* __restrict__ Wkv,
                                const float* __restrict__ Wq,
                                const float* __restrict__ Wrk) {
    int idx = blockIdx.x * blockDim.x + threadIdx.x;
    if (idx >= HDIM * 1536) return;
    int row = idx / 1536;
    int col = idx - row * 1536;
    float v;
    if (col < 256)      v = Wkv[row * 256 + col];
    else if (col < 512) v = Wq[row * 256 + (col - 256)];
    else                v = Wrk[row * 1024 + (col - 512)];
    g_wcat[idx] = to_tf32(v);
}

// ---------------- tf32 GEMM body: 128x128 tile, 3-stage cp.async ----------
#define AST 36
#define BST 136
#define STAGE_F (128 * AST + 32 * BST)   // 8960 floats/stage
#define GEMM_SMEM (3 * STAGE_F * 4)      // 107520 B

__device__ __forceinline__ void gemm_body(
    const float* __restrict__ A, int lda,
    const float* __restrict__ B, int ldb,
    float* __restrict__ C, int ldc,
    int K, int coff, bool split, bool round_out,
    int bm, int bn, float* smem)
{
    const uint32_t sb = smem_u32(smem);
    const int tid  = threadIdx.x;
    const int lane = tid & 31;
    const int wid  = tid >> 5;
    const int wm   = (wid & 1) * 64;
    const int wn   = (wid >> 1) * 32;
    const int g    = lane >> 2;
    const int j    = lane & 3;

    float acc[4][4][4];
#pragma unroll
    for (int mt = 0; mt < 4; mt++)
#pragma unroll
        for (int nt = 0; nt < 4; nt++)
#pragma unroll
            for (int e = 0; e < 4; e++) acc[mt][nt][e] = 0.f;

    const int nstage = K >> 5;

    auto issue = [&](int it) {
        const int k0 = it << 5;
        const uint32_t abase = sb + ((it % 3) * STAGE_F) * 4;
        const uint32_t bbase = abase + 128 * AST * 4;
#pragma unroll
        for (int i = 0; i < 4; i++) {
            int f4 = tid + (i << 8);
            int r = f4 >> 3, c4 = f4 & 7;
            cp16(abase + (uint32_t)(r * AST + c4 * 4) * 4,
                 A + (size_t)(bm + r) * lda + k0 + c4 * 4);
        }
#pragma unroll
        for (int i = 0; i < 4; i++) {
            int f4 = tid + (i << 8);
            int rk = f4 >> 5, c4 = f4 & 31;
            cp16(bbase + (uint32_t)(rk * BST + c4 * 4) * 4,
                 B + (size_t)(k0 + rk) * ldb + bn + c4 * 4);
        }
        cp_commit();
    };

    issue(0);
    if (nstage > 1) issue(1);

    for (int it = 0; it < nstage; it++) {
        if (it + 2 < nstage) issue(it + 2);
        else cp_commit();
        cp_wait<2>();
        __syncthreads();

        const float* As = smem + (it % 3) * STAGE_F;
        const float* Bs = As + 128 * AST;
#pragma unroll
        for (int s = 0; s < 4; s++) {
            const int k = s * 8 + j;
            uint32_t af[4][4], bf[4][2];
#pragma unroll
            for (int mt = 0; mt < 4; mt++) {
                const int r = wm + mt * 16 + g;
                af[mt][0] = __float_as_uint(As[r * AST + k]);
                af[mt][1] = __float_as_uint(As[(r + 8) * AST + k]);
                af[mt][2] = __float_as_uint(As[r * AST + k + 4]);
                af[mt][3] = __float_as_uint(As[(r + 8) * AST + k + 4]);
            }
#pragma unroll
            for (int nt = 0; nt < 4; nt++) {
                const int c = wn + nt * 8 + g;
                bf[nt][0] = __float_as_uint(Bs[k * BST + c]);
                bf[nt][1] = __float_as_uint(Bs[(k + 4) * BST + c]);
            }
#pragma unroll
            for (int mt = 0; mt < 4; mt++)
#pragma unroll
                for (int nt = 0; nt < 4; nt++)
                    mma_tf32(acc[mt][nt], af[mt], bf[nt]);
        }
        __syncthreads();
    }

#pragma unroll
    for (int mt = 0; mt < 4; mt++) {
        int row = bm + wm + mt * 16 + g;
#pragma unroll
        for (int nt = 0; nt < 4; nt++) {
            int n = bn + wn + nt * 8 + j * 2;
            int col = split ? (((n >> 6) << 7) + (n & 63) + coff) : n;
            float2 v0, v1;
            if (round_out) {
                v0 = make_float2(to_tf32(acc[mt][nt][0]), to_tf32(acc[mt][nt][1]));
                v1 = make_float2(to_tf32(acc[mt][nt][2]), to_tf32(acc[mt][nt][3]));
            } else {
                v0 = make_float2(acc[mt][nt][0], acc[mt][nt][1]);
                v1 = make_float2(acc[mt][nt][2], acc[mt][nt][3]);
            }
            *(float2*)(C + (size_t)row * ldc + col) = v0;
            *(float2*)(C + (size_t)(row + 8) * ldc + col) = v1;
        }
    }
}

template<bool ROUND>
__global__ void __launch_bounds__(256, 2) tf32_gemm_kernel(
    const float* __restrict__ A, int lda,
    const float* __restrict__ B, int ldb,
    float* __restrict__ C, int ldc, int K)
{
    extern __shared__ float smem[];
    gemm_body(A, lda, B, ldb, C, ldc, K, 0, false, ROUND,
              blockIdx.y * 128, blockIdx.x * 128, smem);
}

// Fused up-projections: 40 x-blocks. [0,8)=k_c, [8,16)=q_c, [16,24)=q_r, [24,40)=v.
__global__ void __launch_bounds__(256, 2) upproj_kernel(
    const float* __restrict__ p1, const float* __restrict__ wr,
    float* __restrict__ k, float* __restrict__ q,
    float* __restrict__ qr, float* __restrict__ v)
{
    extern __shared__ float smem[];
    const int bx = blockIdx.x;
    const int bm = blockIdx.y * 128;
    const float* A;
    const float* B;
    float* C;
    int ldb, ldc, bn;
    bool split;
    if (bx < 8) {
        A = p1;        B = wr + WKU_OFF; C = k;  ldb = 1024; ldc = HDIM; bn = bx << 7;        split = true;
    } else if (bx < 16) {
        A = p1 + 256;  B = wr + WQU_OFF; C = q;  ldb = 1024; ldc = HDIM; bn = (bx - 8) << 7;  split = true;
    } else if (bx < 24) {
        A = p1 + 256;  B = wr + WRQ_OFF; C = qr; ldb = 1024; ldc = 1024; bn = (bx - 16) << 7; split = false;
    } else {
        A = p1;        B = wr + WVU_OFF; C = v;  ldb = 2048; ldc = HDIM; bn = (bx - 24) << 7; split = false;
    }
    gemm_body(A, 1536, B, ldb, C, ldc, 256, 0, split, true, bm, bn, smem);
}

// ---------------- RoPE (outputs tf32-rounded) ----------------
__global__ void rope_kernel() {
    int idx = blockIdx.x * blockDim.x + threadIdx.x;  // over 4096*16*32
    int isK = blockIdx.y;
    int m   = idx >> 9;
    int rem = idx & 511;
    int h   = rem >> 5;
    int j   = rem & 31;
    int s   = m & (S_LEN - 1);

    float inv = powf(10000.0f, -(float)j * (1.0f / 32.0f));
    float ang = (float)s * inv;
    float sn, cs;
    sincosf(ang, &sn, &cs);

    float x1, x2;
    float* dst;
    if (isK) {
        const float* src = g_p1 + (size_t)m * 1536 + 512 + h * 64;
        x1 = src[j]; x2 = src[j + 32];
        dst = g_k + (size_t)m * HDIM + h * HEADD + 64;
    } else {
        const float* src = g_qr + (size_t)m * 1024 + h * 64;
        x1 = src[j]; x2 = src[j + 32];
        dst = g_q + (size_t)m * HDIM + h * HEADD + 64;
    }
    dst[j]      = to_tf32(x1 * cs - x2 * sn);
    dst[j + 32] = to_tf32(x2 * cs + x1 * sn);
}

// ---------------- Flash attention (tf32 mma.sync, causal, cp.async K/V) ----
#define KS_F 8448
#define VS_F 8704
#define KS0  0
#define KS1  KS_F
#define VS0  (2 * KS_F)
#define VS1  (2 * KS_F + VS_F)
#define PS0  (2 * KS_F + 2 * VS_F)
#define FLASH_SMEM ((2 * KS_F + 2 * VS_F + 8704) * 4)

__global__ void __launch_bounds__(256, 1) flash_mma_kernel(
    const float* __restrict__ Q, const float* __restrict__ Kp,
    const float* __restrict__ Vp, float* __restrict__ Y)
{
    extern __shared__ float sm[];
    const uint32_t sb = smem_u32(sm);
    float* Ps = sm + PS0;

    const int tid  = threadIdx.x;
    const int lane = tid & 31;
    const int w    = tid >> 5;
    const int g    = lane >> 2;
    const int j    = lane & 3;
    const int bh   = blockIdx.y;
    const int b    = bh >> 4;
    const int h    = bh & 15;
    const int qt   = (int)gridDim.x - 1 - (int)blockIdx.x;
    const int q0   = qt << 7;
    const float scale = 0.08838834764831845f;  // 1/sqrt(128)

    const float* Kbase = Kp + (size_t)b * S_LEN * HDIM + h * HEADD;
    const float* Vbase = Vp + (size_t)b * S_LEN * HDIM + h * HEADD;

    // ---- stage Q (pre-rounded) into smem (aliases Ks0/Ks1), extract frags
    const float* Qg = Q + (size_t)(b * S_LEN + q0) * HDIM + h * HEADD;
#pragma unroll
    for (int i = 0; i < 16; i++) {
        int f4 = tid + (i << 8);
        int r = f4 >> 5, c4 = f4 & 31;
        *(float4*)&sm[r * 132 + c4 * 4] = *(const float4*)&Qg[(size_t)r * HDIM + c4 * 4];
    }
    __syncthreads();
    uint32_t qa[16][4];
    {
        const int r0 = w * 16 + g;
#pragma unroll
        for (int ks = 0; ks < 16; ks++) {
            int c = ks * 8 + j;
            qa[ks][0] = __float_as_uint(sm[r0 * 132 + c]);
            qa[ks][1] = __float_as_uint(sm[(r0 + 8) * 132 + c]);
            qa[ks][2] = __float_as_uint(sm[r0 * 132 + c + 4]);
            qa[ks][3] = __float_as_uint(sm[(r0 + 8) * 132 + c + 4]);
        }
    }
    __syncthreads();

    auto issue_kv = [&](int t) {
        const int d = t & 1;
        const float* Kg = Kbase + (size_t)(t << 6) * HDIM;
        const float* Vg = Vbase + (size_t)(t << 6) * HDIM;
        const uint32_t kb = sb + (d ? KS1 : KS0) * 4;
        const uint32_t vb = sb + (d ? VS1 : VS0) * 4;
#pragma unroll
        for (int i = 0; i < 8; i++) {
            int f4 = tid + (i << 8);
            int r = f4 >> 5, c4 = f4 & 31;
            cp16(kb + (uint32_t)(r * 132 + c4 * 4) * 4, Kg + (size_t)r * HDIM + c4 * 4);
            cp16(vb + (uint32_t)(r * 136 + c4 * 4) * 4, Vg + (size_t)r * HDIM + c4 * 4);
        }
        cp_commit();
    };

    float o[16][4];
#pragma unroll
    for (int nt = 0; nt < 16; nt++)
#pragma unroll
        for (int e = 0; e < 4; e++) o[nt][e] = 0.f;
    float m0 = -1e30f, m1 = -1e30f, l0 = 0.f, l1 = 0.f;

    const int nkv = 2 * qt + 2;
    issue_kv(0);

    for (int t = 0; t < nkv; t++) {
        const int kv0 = t << 6;
        if (t + 1 < nkv) issue_kv(t + 1);
        else cp_commit();
        cp_wait<1>();
        __syncthreads();

        const float* Ks = sm + ((t & 1) ? KS1 : KS0);
        const float* Vs = sm + ((t & 1) ? VS1 : VS0);

        // ---- S = Q K^T
        float s[8][4];
#pragma unroll
        for (int nt = 0; nt < 8; nt++)
#pragma unroll
            for (int e = 0; e < 4; e++) s[nt][e] = 0.f;
#pragma unroll
        for (int ks = 0; ks < 16; ks++) {
            const int kc = ks * 8 + j;
#pragma unroll
            for (int nt = 0; nt < 8; nt++) {
                uint32_t bf[2];
                bf[0] = __float_as_uint(Ks[(nt * 8 + g) * 132 + kc]);
                bf[1] = __float_as_uint(Ks[(nt * 8 + g) * 132 + kc + 4]);
                mma_tf32(s[nt], qa[ks], bf);
            }
        }

        // ---- online softmax
        const bool needm = (kv0 + 63 > q0);
        const int gr0 = q0 + w * 16 + g;
        const int gr1 = gr0 + 8;
        float tm0 = -1e30f, tm1 = -1e30f;
#pragma unroll
        for (int nt = 0; nt < 8; nt++) {
            int c0 = kv0 + nt * 8 + 2 * j;
#pragma unroll
            for (int e = 0; e < 2; e++) {
                float v0 = s[nt][e] * scale;
                float v1 = s[nt][2 + e] * scale;
                if (needm) {
                    if (c0 + e > gr0) v0 = -1e30f;
                    if (c0 + e > gr1) v1 = -1e30f;
                }
                s[nt][e] = v0; s[nt][2 + e] = v1;
                tm0 = fmaxf(tm0, v0); tm1 = fmaxf(tm1, v1);
            }
        }
        tm0 = fmaxf(tm0, __shfl_xor_sync(0xffffffffu, tm0, 1));
        tm0 = fmaxf(tm0, __shfl_xor_sync(0xffffffffu, tm0, 2));
        tm1 = fmaxf(tm1, __shfl_xor_sync(0xffffffffu, tm1, 1));
        tm1 = fmaxf(tm1, __shfl_xor_sync(0xffffffffu, tm1, 2));
        const float mn0 = fmaxf(m0, tm0), mn1 = fmaxf(m1, tm1);
        const float cr0 = __expf(m0 - mn0), cr1 = __expf(m1 - mn1);
        float sum0 = 0.f, sum1 = 0.f;
        const int pr0 = w * 16 + g;
#pragma unroll
        for (int nt = 0; nt < 8; nt++) {
            float p0 = __expf(s[nt][0] - mn0);
            float p1 = __expf(s[nt][1] - mn0);
            float p2 = __expf(s[nt][2] - mn1);
            float p3 = __expf(s[nt][3] - mn1);
            sum0 += p0 + p1; sum1 += p2 + p3;
            float2 w0 = make_float2(to_tf32(p0), to_tf32(p1));
            float2 w1 = make_float2(to_tf32(p2), to_tf32(p3));
            *(float2*)&Ps[pr0 * 68 + nt * 8 + 2 * j] = w0;
            *(float2*)&Ps[(pr0 + 8) * 68 + nt * 8 + 2 * j] = w1;
        }
        sum0 += __shfl_xor_sync(0xffffffffu, sum0, 1);
        sum0 += __shfl_xor_sync(0xffffffffu, sum0, 2);
        sum1 += __shfl_xor_sync(0xffffffffu, sum1, 1);
        sum1 += __shfl_xor_sync(0xffffffffu, sum1, 2);
        l0 = l0 * cr0 + sum0; l1 = l1 * cr1 + sum1;
        m0 = mn0; m1 = mn1;
#pragma unroll
        for (int nt = 0; nt < 16; nt++) {
            o[nt][0] *= cr0; o[nt][1] *= cr0;
            o[nt][2] *= cr1; o[nt][3] *= cr1;
        }
        // Ps is produced and consumed by the SAME warp: warp-level sync suffices
        __syncwarp();

        // ---- O += P V
#pragma unroll
        for (int kk = 0; kk < 8; kk++) {
            uint32_t pa[4];
            const int kc = kk * 8 + j;
            pa[0] = __float_as_uint(Ps[(w * 16 + g) * 68 + kc]);
            pa[1] = __float_as_uint(Ps[(w * 16 + g + 8) * 68 + kc]);
            pa[2] = __float_as_uint(Ps[(w * 16 + g) * 68 + kc + 4]);
            pa[3] = __float_as_uint(Ps[(w * 16 + g + 8) * 68 + kc + 4]);
#pragma unroll
            for (int nt = 0; nt < 16; nt++) {
                uint32_t bv[2];
                bv[0] = __float_as_uint(Vs[kc * 136 + nt * 8 + g]);
                bv[1] = __float_as_uint(Vs[(kc + 4) * 136 + nt * 8 + g]);
                mma_tf32(o[nt], pa, bv);
            }
        }
        __syncthreads();  // protects Ks/Vs buffer reuse by next cp.async issue
    }

    // ---- epilogue (rounded: feeds the Wo GEMM)
    const float inv0 = 1.f / l0, inv1 = 1.f / l1;
    const int gr0 = q0 + w * 16 + g;
    float* Y0 = Y + (size_t)(b * S_LEN + gr0) * HDIM + h * HEADD;
    float* Y1 = Y + (size_t)(b * S_LEN + gr0 + 8) * HDIM + h * HEADD;
#pragma unroll
    for (int nt = 0; nt < 16; nt++) {
        int c = nt * 8 + 2 * j;
        *(float2*)&Y0[c] = make_float2(to_tf32(o[nt][0] * inv0), to_tf32(o[nt][1] * inv0));
        *(float2*)&Y1[c] = make_float2(to_tf32(o[nt][2] * inv1), to_tf32(o[nt][3] * inv1));
    }
}

// ---------------- launch ----------------
extern "C" void kernel_launch(void* const* d_in, const int* in_sizes, int n_in,
                              void* d_out, int out_size)
{
    const float* hs   = (const float*)d_in[0];
    const float* Wkv  = (const float*)d_in[1];
    const float* Wq_d = (const float*)d_in[2];
    const float* Wk_u = (const float*)d_in[3];
    const float* Wq_u = (const float*)d_in[4];
    const float* Wv_u = (const float*)d_in[5];
    const float* Wrk  = (const float*)d_in[6];
    const float* Wrq  = (const float*)d_in[7];
    const float* Wo   = (const float*)d_in[8];
    float* out = (float*)d_out;

    float *p_wcat, *p_hs, *p_wr, *p_p1, *p_q, *p_k, *p_v, *p_qr, *p_y;
    cudaGetSymbolAddress((void**)&p_wcat, g_wcat);
    cudaGetSymbolAddress((void**)&p_hs, g_hs);
    cudaGetSymbolAddress((void**)&p_wr, g_wr);
    cudaGetSymbolAddress((void**)&p_p1, g_p1);
    cudaGetSymbolAddress((void**)&p_q, g_q);
    cudaGetSymbolAddress((void**)&p_k, g_k);
    cudaGetSymbolAddress((void**)&p_v, g_v);
    cudaGetSymbolAddress((void**)&p_qr, g_qr);
    cudaGetSymbolAddress((void**)&p_y, g_y);

    cudaFuncSetAttribute(tf32_gemm_kernel<true>,
                         cudaFuncAttributeMaxDynamicSharedMemorySize, GEMM_SMEM);
    cudaFuncSetAttribute(tf32_gemm_kernel<false>,
                         cudaFuncAttributeMaxDynamicSharedMemorySize, GEMM_SMEM);
    cudaFuncSetAttribute(upproj_kernel,
                         cudaFuncAttributeMaxDynamicSharedMemorySize, GEMM_SMEM);
    cudaFuncSetAttribute(flash_mma_kernel,
                         cudaFuncAttributeMaxDynamicSharedMemorySize, FLASH_SMEM);

    // 0. tf32 pre-rounding (2 launches)
    concat_w_kernel<<<(HDIM * 1536) / 256, 256>>>(Wkv, Wq_d, Wrk);
    round_all_kernel<<<13568, 256>>>(hs, Wk_u, Wq_u, Wrq, Wv_u, Wo, p_hs, p_wr);

    // 1. fused down-projection: [4096,2048] @ [2048,1536]
    tf32_gemm_kernel<true><<<dim3(12, 32), 256, GEMM_SMEM>>>(
        p_hs, HDIM, p_wcat, 1536, p_p1, 1536, 2048);

    // 2. all up-projections in one launch (K=256)
    upproj_kernel<<<dim3(40, 32), 256, GEMM_SMEM>>>(p_p1, p_wr, p_k, p_q, p_qr, p_v);

    // 3. RoPE (rounds outputs)
    rope_kernel<<<dim3((MROWS * NHEADS * 32) / 256, 2), 256>>>();

    // 4. causal flash attention
    flash_mma_kernel<<<dim3(S_LEN / 128, BATCH * NHEADS), 256, FLASH_SMEM>>>(
        p_q, p_k, p_v, p_y);

    // 5. output projection: [4096,2048] @ [2048,2048]
    tf32_gemm_kernel<false><<<dim3(16, 32), 256, GEMM_SMEM>>>(
        p_y, HDIM, p_wr + WO_OFF, HDIM, out, HDIM, 2048);
}

// round 7
// speedup vs baseline: 3.9302x; 1.0250x over previous
#include <cuda_runtime.h>
#include <math.h>
#include <stdint.h>

#define S_LEN   2048
#define BATCH   2
#define HDIM    2048
#define NHEADS  16
#define HEADD   128
#define MROWS   (BATCH * S_LEN)   // 4096

// ---------------- scratch ----------------
__device__ float g_wcat[HDIM * 1536];     // [Wkv_d | Wq_d | Wrk] (tf32-rounded)
__device__ float g_hs[MROWS * HDIM];      // tf32-rounded hidden states
__device__ float g_wr[5505024];           // rounded: Wk_u|Wq_u|Wrq|Wv_u|Wo
__device__ float g_p1[MROWS * 1536];      // hs @ Wcat : [kv_d | q_d | k_r]
__device__ float g_q[MROWS * HDIM];       // q in [m][h*128+d] layout
__device__ float g_k[MROWS * HDIM];       // k
__device__ float g_v[MROWS * HDIM];       // v
__device__ float g_qr[MROWS * 1024];      // raw q_r before rope
__device__ float g_y[MROWS * HDIM];       // attention output

#define WKU_OFF 0
#define WQU_OFF 262144
#define WRQ_OFF 524288
#define WVU_OFF 786432
#define WO_OFF  1310720

// ---------------- helpers ----------------
__device__ __forceinline__ float to_tf32(float x) {
    uint32_t u;
    asm("cvt.rna.tf32.f32 %0, %1;" : "=r"(u) : "f"(x));
    return __uint_as_float(u);
}

__device__ __forceinline__ void mma_tf32(float* c, const uint32_t* a, const uint32_t* b) {
    asm volatile(
        "mma.sync.aligned.m16n8k8.row.col.f32.tf32.tf32.f32 "
        "{%0,%1,%2,%3}, {%4,%5,%6,%7}, {%8,%9}, {%0,%1,%2,%3};\n"
        : "+f"(c[0]), "+f"(c[1]), "+f"(c[2]), "+f"(c[3])
        : "r"(a[0]), "r"(a[1]), "r"(a[2]), "r"(a[3]), "r"(b[0]), "r"(b[1]));
}

__device__ __forceinline__ uint32_t smem_u32(const void* p) {
    uint32_t a;
    asm("{ .reg .u64 t; cvta.to.shared.u64 t, %1; cvt.u32.u64 %0, t; }" : "=r"(a) : "l"(p));
    return a;
}

__device__ __forceinline__ void cp16(uint32_t dst, const void* src) {
    asm volatile("cp.async.cg.shared.global [%0], [%1], 16;" :: "r"(dst), "l"(src));
}
__device__ __forceinline__ void cp_commit() {
    asm volatile("cp.async.commit_group;" ::: "memory");
}
template<int N>
__device__ __forceinline__ void cp_wait() {
    asm volatile("cp.async.wait_group %0;" :: "n"(N) : "memory");
}

// ---------------- fused rounding + concat (single launch) ----------------
// float4-unit segments:
//   wcat [0,        786432)  gather Wkv|Wq_d|Wrk -> g_wcat (tf32)
//   hs   [786432,  2883584)  -> g_hs
//   Wk_u [2883584, 2949120)
//   Wq_u [2949120, 3014656)
//   Wrq  [3014656, 3080192)
//   Wv_u [3080192, 3211264)
//   Wo   [3211264, 4259840)  -> g_wr (contiguous)
__global__ void round_all_kernel(const float* __restrict__ hs,
                                 const float* __restrict__ wkv,
                                 const float* __restrict__ wqd,
                                 const float* __restrict__ wku,
                                 const float* __restrict__ wqu,
                                 const float* __restrict__ wrq,
                                 const float* __restrict__ wvu,
                                 const float* __restrict__ wrk,
                                 const float* __restrict__ wo,
                                 float* __restrict__ dwcat,
                                 float* __restrict__ dhs,
                                 float* __restrict__ dwr) {
    int i4 = blockIdx.x * blockDim.x + threadIdx.x;
    if (i4 >= 4259840) return;
    const float* src;
    float* dst;
    if (i4 < 786432) {
        // wcat gather: dst row-major [2048][1536]
        int row = i4 / 384;
        int col = (i4 - row * 384) * 4;
        if (col < 256)      src = wkv + (size_t)row * 256 + col;
        else if (col < 512) src = wqd + (size_t)row * 256 + (col - 256);
        else                src = wrk + (size_t)row * 1024 + (col - 512);
        dst = dwcat + (size_t)i4 * 4;
    } else if (i4 < 2883584) {
        int h4 = i4 - 786432;
        src = hs + (size_t)h4 * 4;
        dst = dhs + (size_t)h4 * 4;
    } else {
        int w4 = i4 - 2883584;
        dst = dwr + (size_t)w4 * 4;
        if (w4 < 65536)        src = wku + (size_t)w4 * 4;
        else if (w4 < 131072)  src = wqu + (size_t)(w4 - 65536) * 4;
        else if (w4 < 196608)  src = wrq + (size_t)(w4 - 131072) * 4;
        else if (w4 < 327680)  src = wvu + (size_t)(w4 - 196608) * 4;
        else                   src = wo  + (size_t)(w4 - 327680) * 4;
    }
    float4 v = *(const float4*)src;
    v.x = to_tf32(v.x); v.y = to_tf32(v.y); v.z = to_tf32(v.z); v.w = to_tf32(v.w);
    *(float4*)dst = v;
}

// ---------------- tf32 GEMM body: 128x128 tile, 4 warps x (64x64) ----------
// LDS:MMA = 1:1. 3-stage cp.async. Inputs pre-rounded tf32.
#define AST 36
#define BST 136
#define STAGE_F (128 * AST + 32 * BST)   // 8960 floats/stage
#define GEMM_SMEM (3 * STAGE_F * 4)      // 107520 B

__device__ __forceinline__ void gemm_body(
    const float* __restrict__ A, int lda,
    const float* __restrict__ B, int ldb,
    float* __restrict__ C, int ldc,
    int K, int coff, bool split, bool round_out,
    int bm, int bn, float* smem)
{
    const uint32_t sb = smem_u32(smem);
    const int tid  = threadIdx.x;
    const int lane = tid & 31;
    const int wid  = tid >> 5;          // 0..3
    const int wm   = (wid & 1) * 64;
    const int wn   = (wid >> 1) * 64;
    const int g    = lane >> 2;
    const int j    = lane & 3;

    float acc[4][8][4];
#pragma unroll
    for (int mt = 0; mt < 4; mt++)
#pragma unroll
        for (int nt = 0; nt < 8; nt++)
#pragma unroll
            for (int e = 0; e < 4; e++) acc[mt][nt][e] = 0.f;

    const int nstage = K >> 5;

    auto issue = [&](int it) {
        const int k0 = it << 5;
        const uint32_t abase = sb + ((it % 3) * STAGE_F) * 4;
        const uint32_t bbase = abase + 128 * AST * 4;
        // A: 128x32 = 1024 float4, 8 per thread
#pragma unroll
        for (int i = 0; i < 8; i++) {
            int f4 = tid + (i << 7);
            int r = f4 >> 3, c4 = f4 & 7;
            cp16(abase + (uint32_t)(r * AST + c4 * 4) * 4,
                 A + (size_t)(bm + r) * lda + k0 + c4 * 4);
        }
        // B: 32x128 = 1024 float4
#pragma unroll
        for (int i = 0; i < 8; i++) {
            int f4 = tid + (i << 7);
            int rk = f4 >> 5, c4 = f4 & 31;
            cp16(bbase + (uint32_t)(rk * BST + c4 * 4) * 4,
                 B + (size_t)(k0 + rk) * ldb + bn + c4 * 4);
        }
        cp_commit();
    };

    issue(0);
    if (nstage > 1) issue(1);

    for (int it = 0; it < nstage; it++) {
        if (it + 2 < nstage) issue(it + 2);
        else cp_commit();
        cp_wait<2>();
        __syncthreads();

        const float* As = smem + (it % 3) * STAGE_F;
        const float* Bs = As + 128 * AST;
#pragma unroll
        for (int s = 0; s < 4; s++) {
            const int k = s * 8 + j;
            uint32_t af[4][4], bf[8][2];
#pragma unroll
            for (int mt = 0; mt < 4; mt++) {
                const int r = wm + mt * 16 + g;
                af[mt][0] = __float_as_uint(As[r * AST + k]);
                af[mt][1] = __float_as_uint(As[(r + 8) * AST + k]);
                af[mt][2] = __float_as_uint(As[r * AST + k + 4]);
                af[mt][3] = __float_as_uint(As[(r + 8) * AST + k + 4]);
            }
#pragma unroll
            for (int nt = 0; nt < 8; nt++) {
                const int c = wn + nt * 8 + g;
                bf[nt][0] = __float_as_uint(Bs[k * BST + c]);
                bf[nt][1] = __float_as_uint(Bs[(k + 4) * BST + c]);
            }
#pragma unroll
            for (int mt = 0; mt < 4; mt++)
#pragma unroll
                for (int nt = 0; nt < 8; nt++)
                    mma_tf32(acc[mt][nt], af[mt], bf[nt]);
        }
        __syncthreads();
    }

#pragma unroll
    for (int mt = 0; mt < 4; mt++) {
        int row = bm + wm + mt * 16 + g;
#pragma unroll
        for (int nt = 0; nt < 8; nt++) {
            int n = bn + wn + nt * 8 + j * 2;
            int col = split ? (((n >> 6) << 7) + (n & 63) + coff) : n;
            float2 v0, v1;
            if (round_out) {
                v0 = make_float2(to_tf32(acc[mt][nt][0]), to_tf32(acc[mt][nt][1]));
                v1 = make_float2(to_tf32(acc[mt][nt][2]), to_tf32(acc[mt][nt][3]));
            } else {
                v0 = make_float2(acc[mt][nt][0], acc[mt][nt][1]);
                v1 = make_float2(acc[mt][nt][2], acc[mt][nt][3]);
            }
            *(float2*)(C + (size_t)row * ldc + col) = v0;
            *(float2*)(C + (size_t)(row + 8) * ldc + col) = v1;
        }
    }
}

template<bool ROUND>
__global__ void __launch_bounds__(128, 2) tf32_gemm_kernel(
    const float* __restrict__ A, int lda,
    const float* __restrict__ B, int ldb,
    float* __restrict__ C, int ldc, int K)
{
    extern __shared__ float smem[];
    gemm_body(A, lda, B, ldb, C, ldc, K, 0, false, ROUND,
              blockIdx.y * 128, blockIdx.x * 128, smem);
}

// Fused up-projections: 40 x-blocks. [0,8)=k_c, [8,16)=q_c, [16,24)=q_r, [24,40)=v.
__global__ void __launch_bounds__(128, 2) upproj_kernel(
    const float* __restrict__ p1, const float* __restrict__ wr,
    float* __restrict__ k, float* __restrict__ q,
    float* __restrict__ qr, float* __restrict__ v)
{
    extern __shared__ float smem[];
    const int bx = blockIdx.x;
    const int bm = blockIdx.y * 128;
    const float* A;
    const float* B;
    float* C;
    int ldb, ldc, bn;
    bool split;
    if (bx < 8) {
        A = p1;        B = wr + WKU_OFF; C = k;  ldb = 1024; ldc = HDIM; bn = bx << 7;        split = true;
    } else if (bx < 16) {
        A = p1 + 256;  B = wr + WQU_OFF; C = q;  ldb = 1024; ldc = HDIM; bn = (bx - 8) << 7;  split = true;
    } else if (bx < 24) {
        A = p1 + 256;  B = wr + WRQ_OFF; C = qr; ldb = 1024; ldc = 1024; bn = (bx - 16) << 7; split = false;
    } else {
        A = p1;        B = wr + WVU_OFF; C = v;  ldb = 2048; ldc = HDIM; bn = (bx - 24) << 7; split = false;
    }
    gemm_body(A, 1536, B, ldb, C, ldc, 256, 0, split, true, bm, bn, smem);
}

// ---------------- RoPE (outputs tf32-rounded) ----------------
__global__ void rope_kernel() {
    int idx = blockIdx.x * blockDim.x + threadIdx.x;  // over 4096*16*32
    int isK = blockIdx.y;
    int m   = idx >> 9;
    int rem = idx & 511;
    int h   = rem >> 5;
    int j   = rem & 31;
    int s   = m & (S_LEN - 1);

    float inv = powf(10000.0f, -(float)j * (1.0f / 32.0f));
    float ang = (float)s * inv;
    float sn, cs;
    sincosf(ang, &sn, &cs);

    float x1, x2;
    float* dst;
    if (isK) {
        const float* src = g_p1 + (size_t)m * 1536 + 512 + h * 64;
        x1 = src[j]; x2 = src[j + 32];
        dst = g_k + (size_t)m * HDIM + h * HEADD + 64;
    } else {
        const float* src = g_qr + (size_t)m * 1024 + h * 64;
        x1 = src[j]; x2 = src[j + 32];
        dst = g_q + (size_t)m * HDIM + h * HEADD + 64;
    }
    dst[j]      = to_tf32(x1 * cs - x2 * sn);
    dst[j + 32] = to_tf32(x2 * cs + x1 * sn);
}

// ---------------- Flash attention (tf32 mma.sync, causal, cp.async K/V) ----
#define KS_F 8448
#define VS_F 8704
#define KS0  0
#define KS1  KS_F
#define VS0  (2 * KS_F)
#define VS1  (2 * KS_F + VS_F)
#define PS0  (2 * KS_F + 2 * VS_F)
#define FLASH_SMEM ((2 * KS_F + 2 * VS_F + 8704) * 4)

__global__ void __launch_bounds__(256, 1) flash_mma_kernel(
    const float* __restrict__ Q, const float* __restrict__ Kp,
    const float* __restrict__ Vp, float* __restrict__ Y)
{
    extern __shared__ float sm[];
    const uint32_t sb = smem_u32(sm);
    float* Ps = sm + PS0;

    const int tid  = threadIdx.x;
    const int lane = tid & 31;
    const int w    = tid >> 5;
    const int g    = lane >> 2;
    const int j    = lane & 3;
    const int bh   = blockIdx.y;
    const int b    = bh >> 4;
    const int h    = bh & 15;
    const int qt   = (int)gridDim.x - 1 - (int)blockIdx.x;
    const int q0   = qt << 7;
    const float scale = 0.08838834764831845f;  // 1/sqrt(128)

    const float* Kbase = Kp + (size_t)b * S_LEN * HDIM + h * HEADD;
    const float* Vbase = Vp + (size_t)b * S_LEN * HDIM + h * HEADD;

    // ---- stage Q (pre-rounded) into smem (aliases Ks0/Ks1), extract frags
    const float* Qg = Q + (size_t)(b * S_LEN + q0) * HDIM + h * HEADD;
#pragma unroll
    for (int i = 0; i < 16; i++) {
        int f4 = tid + (i << 8);
        int r = f4 >> 5, c4 = f4 & 31;
        *(float4*)&sm[r * 132 + c4 * 4] = *(const float4*)&Qg[(size_t)r * HDIM + c4 * 4];
    }
    __syncthreads();
    uint32_t qa[16][4];
    {
        const int r0 = w * 16 + g;
#pragma unroll
        for (int ks = 0; ks < 16; ks++) {
            int c = ks * 8 + j;
            qa[ks][0] = __float_as_uint(sm[r0 * 132 + c]);
            qa[ks][1] = __float_as_uint(sm[(r0 + 8) * 132 + c]);
            qa[ks][2] = __float_as_uint(sm[r0 * 132 + c + 4]);
            qa[ks][3] = __float_as_uint(sm[(r0 + 8) * 132 + c + 4]);
        }
    }
    __syncthreads();

    auto issue_kv = [&](int t) {
        const int d = t & 1;
        const float* Kg = Kbase + (size_t)(t << 6) * HDIM;
        const float* Vg = Vbase + (size_t)(t << 6) * HDIM;
        const uint32_t kb = sb + (d ? KS1 : KS0) * 4;
        const uint32_t vb = sb + (d ? VS1 : VS0) * 4;
#pragma unroll
        for (int i = 0; i < 8; i++) {
            int f4 = tid + (i << 8);
            int r = f4 >> 5, c4 = f4 & 31;
            cp16(kb + (uint32_t)(r * 132 + c4 * 4) * 4, Kg + (size_t)r * HDIM + c4 * 4);
            cp16(vb + (uint32_t)(r * 136 + c4 * 4) * 4, Vg + (size_t)r * HDIM + c4 * 4);
        }
        cp_commit();
    };

    float o[16][4];
#pragma unroll
    for (int nt = 0; nt < 16; nt++)
#pragma unroll
        for (int e = 0; e < 4; e++) o[nt][e] = 0.f;
    float m0 = -1e30f, m1 = -1e30f, l0 = 0.f, l1 = 0.f;

    const int nkv = 2 * qt + 2;
    issue_kv(0);

    for (int t = 0; t < nkv; t++) {
        const int kv0 = t << 6;
        if (t + 1 < nkv) issue_kv(t + 1);
        else cp_commit();
        cp_wait<1>();
        __syncthreads();

        const float* Ks = sm + ((t & 1) ? KS1 : KS0);
        const float* Vs = sm + ((t & 1) ? VS1 : VS0);

        // ---- S = Q K^T
        float s[8][4];
#pragma unroll
        for (int nt = 0; nt < 8; nt++)
#pragma unroll
            for (int e = 0; e < 4; e++) s[nt][e] = 0.f;
#pragma unroll
        for (int ks = 0; ks < 16; ks++) {
            const int kc = ks * 8 + j;
#pragma unroll
            for (int nt = 0; nt < 8; nt++) {
                uint32_t bf[2];
                bf[0] = __float_as_uint(Ks[(nt * 8 + g) * 132 + kc]);
                bf[1] = __float_as_uint(Ks[(nt * 8 + g) * 132 + kc + 4]);
                mma_tf32(s[nt], qa[ks], bf);
            }
        }

        // ---- online softmax
        const bool needm = (kv0 + 63 > q0);
        const int gr0 = q0 + w * 16 + g;
        const int gr1 = gr0 + 8;
        float tm0 = -1e30f, tm1 = -1e30f;
#pragma unroll
        for (int nt = 0; nt < 8; nt++) {
            int c0 = kv0 + nt * 8 + 2 * j;
#pragma unroll
            for (int e = 0; e < 2; e++) {
                float v0 = s[nt][e] * scale;
                float v1 = s[nt][2 + e] * scale;
                if (needm) {
                    if (c0 + e > gr0) v0 = -1e30f;
                    if (c0 + e > gr1) v1 = -1e30f;
                }
                s[nt][e] = v0; s[nt][2 + e] = v1;
                tm0 = fmaxf(tm0, v0); tm1 = fmaxf(tm1, v1);
            }
        }
        tm0 = fmaxf(tm0, __shfl_xor_sync(0xffffffffu, tm0, 1));
        tm0 = fmaxf(tm0, __shfl_xor_sync(0xffffffffu, tm0, 2));
        tm1 = fmaxf(tm1, __shfl_xor_sync(0xffffffffu, tm1, 1));
        tm1 = fmaxf(tm1, __shfl_xor_sync(0xffffffffu, tm1, 2));
        const float mn0 = fmaxf(m0, tm0), mn1 = fmaxf(m1, tm1);
        const float cr0 = __expf(m0 - mn0), cr1 = __expf(m1 - mn1);
        float sum0 = 0.f, sum1 = 0.f;
        const int pr0 = w * 16 + g;
#pragma unroll
        for (int nt = 0; nt < 8; nt++) {
            float p0 = __expf(s[nt][0] - mn0);
            float p1 = __expf(s[nt][1] - mn0);
            float p2 = __expf(s[nt][2] - mn1);
            float p3 = __expf(s[nt][3] - mn1);
            sum0 += p0 + p1; sum1 += p2 + p3;
            float2 w0 = make_float2(to_tf32(p0), to_tf32(p1));
            float2 w1 = make_float2(to_tf32(p2), to_tf32(p3));
            *(float2*)&Ps[pr0 * 68 + nt * 8 + 2 * j] = w0;
            *(float2*)&Ps[(pr0 + 8) * 68 + nt * 8 + 2 * j] = w1;
        }
        sum0 += __shfl_xor_sync(0xffffffffu, sum0, 1);
        sum0 += __shfl_xor_sync(0xffffffffu, sum0, 2);
        sum1 += __shfl_xor_sync(0xffffffffu, sum1, 1);
        sum1 += __shfl_xor_sync(0xffffffffu, sum1, 2);
        l0 = l0 * cr0 + sum0; l1 = l1 * cr1 + sum1;
        m0 = mn0; m1 = mn1;
#pragma unroll
        for (int nt = 0; nt < 16; nt++) {
            o[nt][0] *= cr0; o[nt][1] *= cr0;
            o[nt][2] *= cr1; o[nt][3] *= cr1;
        }
        // Ps is produced and consumed by the SAME warp
        __syncwarp();

        // ---- O += P V
#pragma unroll
        for (int kk = 0; kk < 8; kk++) {
            uint32_t pa[4];
            const int kc = kk * 8 + j;
            pa[0] = __float_as_uint(Ps[(w * 16 + g) * 68 + kc]);
            pa[1] = __float_as_uint(Ps[(w * 16 + g + 8) * 68 + kc]);
            pa[2] = __float_as_uint(Ps[(w * 16 + g) * 68 + kc + 4]);
            pa[3] = __float_as_uint(Ps[(w * 16 + g + 8) * 68 + kc + 4]);
#pragma unroll
            for (int nt = 0; nt < 16; nt++) {
                uint32_t bv[2];
                bv[0] = __float_as_uint(Vs[kc * 136 + nt * 8 + g]);
                bv[1] = __float_as_uint(Vs[(kc + 4) * 136 + nt * 8 + g]);
                mma_tf32(o[nt], pa, bv);
            }
        }
        __syncthreads();  // protects Ks/Vs buffer reuse by next cp.async issue
    }

    // ---- epilogue (rounded: feeds the Wo GEMM)
    const float inv0 = 1.f / l0, inv1 = 1.f / l1;
    const int gr0 = q0 + w * 16 + g;
    float* Y0 = Y + (size_t)(b * S_LEN + gr0) * HDIM + h * HEADD;
    float* Y1 = Y + (size_t)(b * S_LEN + gr0 + 8) * HDIM + h * HEADD;
#pragma unroll
    for (int nt = 0; nt < 16; nt++) {
        int c = nt * 8 + 2 * j;
        *(float2*)&Y0[c] = make_float2(to_tf32(o[nt][0] * inv0), to_tf32(o[nt][1] * inv0));
        *(float2*)&Y1[c] = make_float2(to_tf32(o[nt][2] * inv1), to_tf32(o[nt][3] * inv1));
    }
}

// ---------------- launch ----------------
extern "C" void kernel_launch(void* const* d_in, const int* in_sizes, int n_in,
                              void* d_out, int out_size)
{
    const float* hs   = (const float*)d_in[0];
    const float* Wkv  = (const float*)d_in[1];
    const float* Wq_d = (const float*)d_in[2];
    const float* Wk_u = (const float*)d_in[3];
    const float* Wq_u = (const float*)d_in[4];
    const float* Wv_u = (const float*)d_in[5];
    const float* Wrk  = (const float*)d_in[6];
    const float* Wrq  = (const float*)d_in[7];
    const float* Wo   = (const float*)d_in[8];
    float* out = (float*)d_out;

    float *p_wcat, *p_hs, *p_wr, *p_p1, *p_q, *p_k, *p_v, *p_qr, *p_y;
    cudaGetSymbolAddress((void**)&p_wcat, g_wcat);
    cudaGetSymbolAddress((void**)&p_hs, g_hs);
    cudaGetSymbolAddress((void**)&p_wr, g_wr);
    cudaGetSymbolAddress((void**)&p_p1, g_p1);
    cudaGetSymbolAddress((void**)&p_q, g_q);
    cudaGetSymbolAddress((void**)&p_k, g_k);
    cudaGetSymbolAddress((void**)&p_v, g_v);
    cudaGetSymbolAddress((void**)&p_qr, g_qr);
    cudaGetSymbolAddress((void**)&p_y, g_y);

    cudaFuncSetAttribute(tf32_gemm_kernel<true>,
                         cudaFuncAttributeMaxDynamicSharedMemorySize, GEMM_SMEM);
    cudaFuncSetAttribute(tf32_gemm_kernel<false>,
                         cudaFuncAttributeMaxDynamicSharedMemorySize, GEMM_SMEM);
    cudaFuncSetAttribute(upproj_kernel,
                         cudaFuncAttributeMaxDynamicSharedMemorySize, GEMM_SMEM);
    cudaFuncSetAttribute(flash_mma_kernel,
                         cudaFuncAttributeMaxDynamicSharedMemorySize, FLASH_SMEM);

    // 0. fused tf32 pre-rounding + weight concat (one launch)
    round_all_kernel<<<16640, 256>>>(hs, Wkv, Wq_d, Wk_u, Wq_u, Wrq, Wv_u, Wrk, Wo,
                                     p_wcat, p_hs, p_wr);

    // 1. fused down-projection: [4096,2048] @ [2048,1536]
    tf32_gemm_kernel<true><<<dim3(12, 32), 128, GEMM_SMEM>>>(
        p_hs, HDIM, p_wcat, 1536, p_p1, 1536, 2048);

    // 2. all up-projections in one launch (K=256)
    upproj_kernel<<<dim3(40, 32), 128, GEMM_SMEM>>>(p_p1, p_wr, p_k, p_q, p_qr, p_v);

    // 3. RoPE (rounds outputs)
    rope_kernel<<<dim3((MROWS * NHEADS * 32) / 256, 2), 256>>>();

    // 4. causal flash attention
    flash_mma_kernel<<<dim3(S_LEN / 128, BATCH * NHEADS), 256, FLASH_SMEM>>>(
        p_q, p_k, p_v, p_y);

    // 5. output projection: [4096,2048] @ [2048,2048]
    tf32_gemm_kernel<false><<<dim3(16, 32), 128, GEMM_SMEM>>>(
        p_y, HDIM, p_wr + WO_OFF, HDIM, out, HDIM, 2048);
}

// round 8
// speedup vs baseline: 6.5889x; 1.6765x over previous
#include <cuda_runtime.h>
#include <cuda_fp16.h>
#include <math.h>
#include <stdint.h>

#define S_LEN   2048
#define BATCH   2
#define HDIM    2048
#define NHEADS  16
#define MROWS   (BATCH * S_LEN)   // 4096

// ---------------- scratch (half) ----------------
__device__ __half g_wh[8650752];   // transposed half weights (see offsets)
__device__ __half g_hs[8388608];   // hs [4096][2048]
__device__ __half g_p1[6291456];   // [4096][1536] = kv_d|q_d|k_r
__device__ __half g_q [8388608];   // [m][h*128+d]
__device__ __half g_k [8388608];
__device__ __half g_vt[8388608];   // TRANSPOSED: [n=2048][m=4096]
__device__ __half g_qr[4194304];   // [m][1024]
__device__ __half g_y [8388608];

// g_wh offsets (halves)
#define WCAT_OFF 0u         // [1536][2048]
#define WKU_OFF  3145728u   // [1024][256]
#define WQU_OFF  3407872u
#define WRQ_OFF  3670016u
#define WVU_OFF  3932160u   // [2048][256]
#define WO_OFF   4456448u   // [2048][2048]

// ---------------- helpers ----------------
__device__ __forceinline__ void mma_f16(float* c, const uint32_t* a, const uint32_t* b) {
    asm volatile(
        "mma.sync.aligned.m16n8k16.row.col.f32.f16.f16.f32 "
        "{%0,%1,%2,%3}, {%4,%5,%6,%7}, {%8,%9}, {%0,%1,%2,%3};\n"
        : "+f"(c[0]), "+f"(c[1]), "+f"(c[2]), "+f"(c[3])
        : "r"(a[0]), "r"(a[1]), "r"(a[2]), "r"(a[3]), "r"(b[0]), "r"(b[1]));
}
__device__ __forceinline__ uint32_t pack2(float a, float b) {
    __half2 h = __floats2half2_rn(a, b);
    return *(uint32_t*)&h;
}
__device__ __forceinline__ uint32_t smem_u32(const void* p) {
    uint32_t a;
    asm("{ .reg .u64 t; cvta.to.shared.u64 t, %1; cvt.u32.u64 %0, t; }" : "=r"(a) : "l"(p));
    return a;
}
__device__ __forceinline__ void cp16(uint32_t dst, const void* src) {
    asm volatile("cp.async.cg.shared.global [%0], [%1], 16;" :: "r"(dst), "l"(src));
}
__device__ __forceinline__ void cp_commit() {
    asm volatile("cp.async.commit_group;" ::: "memory");
}
template<int N>
__device__ __forceinline__ void cp_wait() {
    asm volatile("cp.async.wait_group %0;" :: "n"(N) : "memory");
}

// ---------------- hs -> half ----------------
__global__ void hs_half_kernel(const float* __restrict__ src, __half* __restrict__ dst) {
    int i = blockIdx.x * blockDim.x + threadIdx.x;  // over 1048576, 8 floats each
    float4 a = ((const float4*)src)[2 * i];
    float4 b = ((const float4*)src)[2 * i + 1];
    uint4 u;
    u.x = pack2(a.x, a.y); u.y = pack2(a.z, a.w);
    u.z = pack2(b.x, b.y); u.w = pack2(b.z, b.w);
    *(uint4*)&dst[8 * i] = u;
}

// ---------------- weight transpose + round to half ----------------
// dstT[n][k] = src[k][n]. 32x32 tiles, block (32,8).
__global__ void transpose_round_kernel(
    const float* __restrict__ wkv, const float* __restrict__ wqd,
    const float* __restrict__ wrk, const float* __restrict__ wku,
    const float* __restrict__ wqu, const float* __restrict__ wrq,
    const float* __restrict__ wvu, const float* __restrict__ wo,
    __half* __restrict__ wh)
{
    __shared__ float tile[32][33];
    const int b  = blockIdx.x;
    const int tx = threadIdx.x;
    const int ty = threadIdx.y;

    const float* src; int ld, k0, n0, dK; uint32_t doff;
    if (b < 3072) {            // wcat gather: K=2048, N=1536
        k0 = (b / 48) * 32; n0 = (b % 48) * 32; doff = WCAT_OFF; dK = 2048;
        if (n0 < 256)      { src = wkv + n0;         ld = 256; }
        else if (n0 < 512) { src = wqd + (n0 - 256); ld = 256; }
        else               { src = wrk + (n0 - 512); ld = 1024; }
    } else if (b < 3328) { int l = b - 3072; k0 = (l / 32) * 32; n0 = (l % 32) * 32;
        src = wku + n0; ld = 1024; doff = WKU_OFF; dK = 256;
    } else if (b < 3584) { int l = b - 3328; k0 = (l / 32) * 32; n0 = (l % 32) * 32;
        src = wqu + n0; ld = 1024; doff = WQU_OFF; dK = 256;
    } else if (b < 3840) { int l = b - 3584; k0 = (l / 32) * 32; n0 = (l % 32) * 32;
        src = wrq + n0; ld = 1024; doff = WRQ_OFF; dK = 256;
    } else if (b < 4352) { int l = b - 3840; k0 = (l / 64) * 32; n0 = (l % 64) * 32;
        src = wvu + n0; ld = 2048; doff = WVU_OFF; dK = 256;
    } else {               int l = b - 4352; k0 = (l / 64) * 32; n0 = (l % 64) * 32;
        src = wo + n0;  ld = 2048; doff = WO_OFF;  dK = 2048;
    }

#pragma unroll
    for (int rr = 0; rr < 4; rr++) {
        int r = ty * 4 + rr;
        tile[r][tx] = src[(size_t)(k0 + r) * ld + tx];
    }
    __syncthreads();
#pragma unroll
    for (int rr = 0; rr < 4; rr++) {
        int r = ty * 4 + rr;
        wh[doff + (size_t)(n0 + r) * dK + k0 + tx] = __float2half_rn(tile[tx][r]);
    }
}

// ---------------- fp16 GEMM: 128x128 tile, 4-stage cp.async, 4 warps 64x64 ----
// A half [M][lda] k-major; B half [N][ldb] k-major (pre-transposed).
#define HKP 40
#define HSTG (2 * 128 * HKP)        // halves per stage = 10240
#define GEMM_SMEM (4 * HSTG * 2)    // 81920 B

// mode: 0 = half plain, 1 = half split(head interleave), 2 = f32 plain, 3 = half V-transposed
__device__ __forceinline__ void gemm_f16_body(
    const __half* __restrict__ A, int lda,
    const __half* __restrict__ B, int ldb,
    void* Cv, int ldc, int K, int mode,
    int bm, int bn, __half* smem)
{
    const uint32_t sb = smem_u32(smem);
    const int tid  = threadIdx.x;
    const int lane = tid & 31;
    const int wid  = tid >> 5;
    const int wm   = (wid & 1) * 64;
    const int wn   = (wid >> 1) * 64;
    const int g    = lane >> 2;
    const int j    = lane & 3;

    float acc[4][8][4];
#pragma unroll
    for (int mt = 0; mt < 4; mt++)
#pragma unroll
        for (int nt = 0; nt < 8; nt++)
#pragma unroll
            for (int e = 0; e < 4; e++) acc[mt][nt][e] = 0.f;

    const int nstage = K >> 5;

    auto issue = [&](int it) {
        const int k0 = it << 5;
        const uint32_t base = sb + ((it & 3) * HSTG) * 2;
#pragma unroll
        for (int i = 0; i < 4; i++) {
            int f = tid + (i << 7);
            int r = f >> 2, c = f & 3;
            cp16(base + (uint32_t)(r * HKP + c * 8) * 2,
                 A + (size_t)(bm + r) * lda + k0 + c * 8);
        }
#pragma unroll
        for (int i = 0; i < 4; i++) {
            int f = tid + (i << 7);
            int r = f >> 2, c = f & 3;
            cp16(base + (uint32_t)(128 * HKP + r * HKP + c * 8) * 2,
                 B + (size_t)(bn + r) * ldb + k0 + c * 8);
        }
        cp_commit();
    };

    issue(0);
    if (nstage > 1) issue(1);
    if (nstage > 2) issue(2);

    for (int it = 0; it < nstage; it++) {
        if (it + 3 < nstage) issue(it + 3);
        else cp_commit();
        cp_wait<3>();
        __syncthreads();

        const __half* As = smem + (it & 3) * HSTG;
        const __half* Bs = As + 128 * HKP;
#pragma unroll
        for (int s = 0; s < 2; s++) {
            const int kb = s * 16;
            uint32_t af[4][4], bf[8][2];
#pragma unroll
            for (int mt = 0; mt < 4; mt++) {
                const int r = wm + mt * 16 + g;
                af[mt][0] = *(const uint32_t*)&As[r * HKP + kb + 2 * j];
                af[mt][1] = *(const uint32_t*)&As[(r + 8) * HKP + kb + 2 * j];
                af[mt][2] = *(const uint32_t*)&As[r * HKP + kb + 2 * j + 8];
                af[mt][3] = *(const uint32_t*)&As[(r + 8) * HKP + kb + 2 * j + 8];
            }
#pragma unroll
            for (int nt = 0; nt < 8; nt++) {
                const int c = wn + nt * 8 + g;
                bf[nt][0] = *(const uint32_t*)&Bs[c * HKP + kb + 2 * j];
                bf[nt][1] = *(const uint32_t*)&Bs[c * HKP + kb + 2 * j + 8];
            }
#pragma unroll
            for (int mt = 0; mt < 4; mt++)
#pragma unroll
                for (int nt = 0; nt < 8; nt++)
                    mma_f16(acc[mt][nt], af[mt], bf[nt]);
        }
        __syncthreads();
    }

    // epilogue
#pragma unroll
    for (int mt = 0; mt < 4; mt++) {
        const int row = bm + wm + mt * 16 + g;
#pragma unroll
        for (int nt = 0; nt < 8; nt++) {
            const int n = bn + wn + nt * 8 + 2 * j;
            if (mode == 3) {
                __half* vt = (__half*)Cv;
                vt[(size_t)n * 4096 + row]           = __float2half_rn(acc[mt][nt][0]);
                vt[(size_t)(n + 1) * 4096 + row]     = __float2half_rn(acc[mt][nt][1]);
                vt[(size_t)n * 4096 + row + 8]       = __float2half_rn(acc[mt][nt][2]);
                vt[(size_t)(n + 1) * 4096 + row + 8] = __float2half_rn(acc[mt][nt][3]);
            } else if (mode == 2) {
                float* C = (float*)Cv;
                *(float2*)(C + (size_t)row * ldc + n) =
                    make_float2(acc[mt][nt][0], acc[mt][nt][1]);
                *(float2*)(C + (size_t)(row + 8) * ldc + n) =
                    make_float2(acc[mt][nt][2], acc[mt][nt][3]);
            } else {
                const int col = (mode == 1) ? (((n >> 6) << 7) + (n & 63)) : n;
                __half* C = (__half*)Cv;
                *(uint32_t*)(C + (size_t)row * ldc + col) = pack2(acc[mt][nt][0], acc[mt][nt][1]);
                *(uint32_t*)(C + (size_t)(row + 8) * ldc + col) = pack2(acc[mt][nt][2], acc[mt][nt][3]);
            }
        }
    }
}

__global__ void __launch_bounds__(128, 2) f16_gemm_kernel(
    const __half* A, int lda, const __half* B, int ldb,
    void* C, int ldc, int K, int mode)
{
    extern __shared__ __half smh[];
    gemm_f16_body(A, lda, B, ldb, C, ldc, K, mode,
                  blockIdx.y * 128, blockIdx.x * 128, smh);
}

// Fused up-projections: 40 x-blocks. [0,8)=k_c [8,16)=q_c [16,24)=q_r [24,40)=v.
__global__ void __launch_bounds__(128, 2) upproj_kernel(
    const __half* __restrict__ p1, const __half* __restrict__ wh,
    __half* __restrict__ k, __half* __restrict__ q,
    __half* __restrict__ qr, __half* __restrict__ vt)
{
    extern __shared__ __half smh[];
    const int bx = blockIdx.x;
    const int bm = blockIdx.y * 128;
    const __half* A;
    const __half* B;
    void* C;
    int ldb, ldc, bn, mode;
    if (bx < 8) {
        A = p1;       B = wh + WKU_OFF; C = k;  ldb = 256; ldc = HDIM; bn = bx << 7;        mode = 1;
    } else if (bx < 16) {
        A = p1 + 256; B = wh + WQU_OFF; C = q;  ldb = 256; ldc = HDIM; bn = (bx - 8) << 7;  mode = 1;
    } else if (bx < 24) {
        A = p1 + 256; B = wh + WRQ_OFF; C = qr; ldb = 256; ldc = 1024; bn = (bx - 16) << 7; mode = 0;
    } else {
        A = p1;       B = wh + WVU_OFF; C = vt; ldb = 256; ldc = 0;    bn = (bx - 24) << 7; mode = 3;
    }
    gemm_f16_body(A, 1536, B, ldb, C, ldc, 256, mode, bm, bn, smh);
}

// ---------------- RoPE (half in/out) ----------------
__global__ void rope_kernel() {
    int idx = blockIdx.x * blockDim.x + threadIdx.x;
    int isK = blockIdx.y;
    int m   = idx >> 9;
    int rem = idx & 511;
    int h   = rem >> 5;
    int j   = rem & 31;
    int s   = m & (S_LEN - 1);

    // 1/10000^(j/32) = 2^(-j*log2(1e4)/32)
    float inv = exp2f(-0.41524101186092f * (float)j);
    float ang = (float)s * inv;
    float sn, cs;
    sincosf(ang, &sn, &cs);

    float x1, x2;
    __half* dst;
    if (isK) {
        const __half* src = g_p1 + (size_t)m * 1536 + 512 + h * 64;
        x1 = __half2float(src[j]); x2 = __half2float(src[j + 32]);
        dst = g_k + (size_t)m * HDIM + h * 128 + 64;
    } else {
        const __half* src = g_qr + (size_t)m * 1024 + h * 64;
        x1 = __half2float(src[j]); x2 = __half2float(src[j + 32]);
        dst = g_q + (size_t)m * HDIM + h * 128 + 64;
    }
    dst[j]      = __float2half_rn(x1 * cs - x2 * sn);
    dst[j + 32] = __float2half_rn(x2 * cs + x1 * sn);
}

// ---------------- Flash attention (fp16 mma, causal, cp.async) ----------------
// BQ=128, BK=64, d=128, 256 thr = 8 warps x 16 rows.
// smem halves: Ks 2x[64][136], Vt 2x[128][72], Ps [128][72]
#define FKS0 0
#define FKS1 8704
#define FVT0 17408
#define FVT1 26624
#define FPS  35840
#define FLASH_SMEM (45056 * 2)

__global__ void __launch_bounds__(256, 1) flash_f16_kernel(
    const __half* __restrict__ Q, const __half* __restrict__ Kp,
    const __half* __restrict__ Vt, __half* __restrict__ Y)
{
    extern __shared__ __half smh[];
    const uint32_t sb = smem_u32(smh);
    __half* Ps = smh + FPS;

    const int tid  = threadIdx.x;
    const int lane = tid & 31;
    const int w    = tid >> 5;
    const int g    = lane >> 2;
    const int j    = lane & 3;
    const int bh   = blockIdx.y;
    const int b    = bh >> 4;
    const int h    = bh & 15;
    const int qt   = (int)gridDim.x - 1 - (int)blockIdx.x;
    const int q0   = qt << 7;
    const float scale = 0.08838834764831845f;

    const __half* Kbase = Kp + (size_t)b * S_LEN * HDIM + h * 128;
    const __half* Vtb   = Vt + (size_t)h * 128 * 4096 + b * S_LEN;

    // ---- stage Q [128][136] into Ks region, extract persistent A-frags
    const __half* Qg = Q + (size_t)(b * S_LEN + q0) * HDIM + h * 128;
#pragma unroll
    for (int i = 0; i < 8; i++) {
        int f = tid + (i << 8);
        int r = f >> 4, c = f & 15;
        cp16(sb + (uint32_t)(r * 136 + c * 8) * 2, Qg + (size_t)r * HDIM + c * 8);
    }
    cp_commit();
    cp_wait<0>();
    __syncthreads();

    uint32_t qa[8][4];
    {
        const int r0 = w * 16 + g;
#pragma unroll
        for (int ks = 0; ks < 8; ks++) {
            const int c = ks * 16 + 2 * j;
            qa[ks][0] = *(const uint32_t*)&smh[r0 * 136 + c];
            qa[ks][1] = *(const uint32_t*)&smh[(r0 + 8) * 136 + c];
            qa[ks][2] = *(const uint32_t*)&smh[r0 * 136 + c + 8];
            qa[ks][3] = *(const uint32_t*)&smh[(r0 + 8) * 136 + c + 8];
        }
    }
    __syncthreads();

    auto issue_kv = [&](int t) {
        const int d = t & 1;
        const int kv0 = t << 6;
        const uint32_t kb = sb + (d ? FKS1 : FKS0) * 2;
        const uint32_t vb = sb + (d ? FVT1 : FVT0) * 2;
#pragma unroll
        for (int i = 0; i < 4; i++) {
            int f = tid + (i << 8);
            int r = f >> 4, c = f & 15;
            cp16(kb + (uint32_t)(r * 136 + c * 8) * 2,
                 Kbase + (size_t)(kv0 + r) * HDIM + c * 8);
        }
#pragma unroll
        for (int i = 0; i < 4; i++) {
            int f = tid + (i << 8);
            int r = f >> 3, c = f & 7;
            cp16(vb + (uint32_t)(r * 72 + c * 8) * 2,
                 Vtb + (size_t)r * 4096 + kv0 + c * 8);
        }
        cp_commit();
    };

    float o[16][4];
#pragma unroll
    for (int nt = 0; nt < 16; nt++)
#pragma unroll
        for (int e = 0; e < 4; e++) o[nt][e] = 0.f;
    float m0 = -1e30f, m1 = -1e30f, l0 = 0.f, l1 = 0.f;

    const int nkv = 2 * qt + 2;
    issue_kv(0);

    for (int t = 0; t < nkv; t++) {
        const int kv0 = t << 6;
        if (t + 1 < nkv) issue_kv(t + 1);
        else cp_commit();
        cp_wait<1>();
        __syncthreads();

        const __half* Ks = smh + ((t & 1) ? FKS1 : FKS0);
        const __half* Vs = smh + ((t & 1) ? FVT1 : FVT0);

        // ---- S = Q K^T
        float s[8][4];
#pragma unroll
        for (int nt = 0; nt < 8; nt++)
#pragma unroll
            for (int e = 0; e < 4; e++) s[nt][e] = 0.f;
#pragma unroll
        for (int ks = 0; ks < 8; ks++) {
            const int kc = ks * 16 + 2 * j;
#pragma unroll
            for (int nt = 0; nt < 8; nt++) {
                uint32_t bf[2];
                bf[0] = *(const uint32_t*)&Ks[(nt * 8 + g) * 136 + kc];
                bf[1] = *(const uint32_t*)&Ks[(nt * 8 + g) * 136 + kc + 8];
                mma_f16(s[nt], qa[ks], bf);
            }
        }

        // ---- online softmax (fp32)
        const bool needm = (kv0 + 63 > q0);
        const int gr0 = q0 + w * 16 + g;
        const int gr1 = gr0 + 8;
        float tm0 = -1e30f, tm1 = -1e30f;
#pragma unroll
        for (int nt = 0; nt < 8; nt++) {
            int c0 = kv0 + nt * 8 + 2 * j;
#pragma unroll
            for (int e = 0; e < 2; e++) {
                float v0 = s[nt][e] * scale;
                float v1 = s[nt][2 + e] * scale;
                if (needm) {
                    if (c0 + e > gr0) v0 = -1e30f;
                    if (c0 + e > gr1) v1 = -1e30f;
                }
                s[nt][e] = v0; s[nt][2 + e] = v1;
                tm0 = fmaxf(tm0, v0); tm1 = fmaxf(tm1, v1);
            }
        }
        tm0 = fmaxf(tm0, __shfl_xor_sync(0xffffffffu, tm0, 1));
        tm0 = fmaxf(tm0, __shfl_xor_sync(0xffffffffu, tm0, 2));
        tm1 = fmaxf(tm1, __shfl_xor_sync(0xffffffffu, tm1, 1));
        tm1 = fmaxf(tm1, __shfl_xor_sync(0xffffffffu, tm1, 2));
        const float mn0 = fmaxf(m0, tm0), mn1 = fmaxf(m1, tm1);
        const float cr0 = __expf(m0 - mn0), cr1 = __expf(m1 - mn1);
        float sum0 = 0.f, sum1 = 0.f;
        const int pr0 = w * 16 + g;
#pragma unroll
        for (int nt = 0; nt < 8; nt++) {
            float p0 = __expf(s[nt][0] - mn0);
            float p1 = __expf(s[nt][1] - mn0);
            float p2 = __expf(s[nt][2] - mn1);
            float p3 = __expf(s[nt][3] - mn1);
            sum0 += p0 + p1; sum1 += p2 + p3;
            *(uint32_t*)&Ps[pr0 * 72 + nt * 8 + 2 * j] = pack2(p0, p1);
            *(uint32_t*)&Ps[(pr0 + 8) * 72 + nt * 8 + 2 * j] = pack2(p2, p3);
        }
        sum0 += __shfl_xor_sync(0xffffffffu, sum0, 1);
        sum0 += __shfl_xor_sync(0xffffffffu, sum0, 2);
        sum1 += __shfl_xor_sync(0xffffffffu, sum1, 1);
        sum1 += __shfl_xor_sync(0xffffffffu, sum1, 2);
        l0 = l0 * cr0 + sum0; l1 = l1 * cr1 + sum1;
        m0 = mn0; m1 = mn1;
#pragma unroll
        for (int nt = 0; nt < 16; nt++) {
            o[nt][0] *= cr0; o[nt][1] *= cr0;
            o[nt][2] *= cr1; o[nt][3] *= cr1;
        }
        __syncwarp();  // Ps produced+consumed by same warp

        // ---- O += P V  (Vt rows are d-dims)
#pragma unroll
        for (int kk = 0; kk < 4; kk++) {
            uint32_t pa[4];
            const int kc = kk * 16 + 2 * j;
            pa[0] = *(const uint32_t*)&Ps[(w * 16 + g) * 72 + kc];
            pa[1] = *(const uint32_t*)&Ps[(w * 16 + g + 8) * 72 + kc];
            pa[2] = *(const uint32_t*)&Ps[(w * 16 + g) * 72 + kc + 8];
            pa[3] = *(const uint32_t*)&Ps[(w * 16 + g + 8) * 72 + kc + 8];
#pragma unroll
            for (int nt = 0; nt < 16; nt++) {
                uint32_t bv[2];
                bv[0] = *(const uint32_t*)&Vs[(nt * 8 + g) * 72 + kc];
                bv[1] = *(const uint32_t*)&Vs[(nt * 8 + g) * 72 + kc + 8];
                mma_f16(o[nt], pa, bv);
            }
        }
        __syncthreads();  // protect K/V buffers before next issue
    }

    // ---- epilogue -> y half
    const float inv0 = 1.f / l0, inv1 = 1.f / l1;
    const int gr0 = q0 + w * 16 + g;
    __half* Y0 = Y + (size_t)(b * S_LEN + gr0) * HDIM + h * 128;
    __half* Y1 = Y + (size_t)(b * S_LEN + gr0 + 8) * HDIM + h * 128;
#pragma unroll
    for (int nt = 0; nt < 16; nt++) {
        const int c = nt * 8 + 2 * j;
        *(uint32_t*)&Y0[c] = pack2(o[nt][0] * inv0, o[nt][1] * inv0);
        *(uint32_t*)&Y1[c] = pack2(o[nt][2] * inv1, o[nt][3] * inv1);
    }
}

// ---------------- launch ----------------
extern "C" void kernel_launch(void* const* d_in, const int* in_sizes, int n_in,
                              void* d_out, int out_size)
{
    const float* hs   = (const float*)d_in[0];
    const float* Wkv  = (const float*)d_in[1];
    const float* Wq_d = (const float*)d_in[2];
    const float* Wk_u = (const float*)d_in[3];
    const float* Wq_u = (const float*)d_in[4];
    const float* Wv_u = (const float*)d_in[5];
    const float* Wrk  = (const float*)d_in[6];
    const float* Wrq  = (const float*)d_in[7];
    const float* Wo   = (const float*)d_in[8];
    float* out = (float*)d_out;

    __half *p_wh, *p_hs, *p_p1, *p_q, *p_k, *p_vt, *p_qr, *p_y;
    cudaGetSymbolAddress((void**)&p_wh, g_wh);
    cudaGetSymbolAddress((void**)&p_hs, g_hs);
    cudaGetSymbolAddress((void**)&p_p1, g_p1);
    cudaGetSymbolAddress((void**)&p_q, g_q);
    cudaGetSymbolAddress((void**)&p_k, g_k);
    cudaGetSymbolAddress((void**)&p_vt, g_vt);
    cudaGetSymbolAddress((void**)&p_qr, g_qr);
    cudaGetSymbolAddress((void**)&p_y, g_y);

    cudaFuncSetAttribute(f16_gemm_kernel,
                         cudaFuncAttributeMaxDynamicSharedMemorySize, GEMM_SMEM);
    cudaFuncSetAttribute(upproj_kernel,
                         cudaFuncAttributeMaxDynamicSharedMemorySize, GEMM_SMEM);
    cudaFuncSetAttribute(flash_f16_kernel,
                         cudaFuncAttributeMaxDynamicSharedMemorySize, FLASH_SMEM);

    // 0. input conversion: hs->half, weights -> transposed half
    hs_half_kernel<<<4096, 256>>>(hs, p_hs);
    transpose_round_kernel<<<8448, dim3(32, 8)>>>(Wkv, Wq_d, Wrk, Wk_u, Wq_u,
                                                  Wrq, Wv_u, Wo, p_wh);

    // 1. down-projection: [4096,2048] @ [2048,1536] -> p1 (half)
    f16_gemm_kernel<<<dim3(12, 32), 128, GEMM_SMEM>>>(
        p_hs, HDIM, p_wh + WCAT_OFF, 2048, p_p1, 1536, 2048, 0);

    // 2. fused up-projections (K=256): k_c, q_c, q_r, v(transposed)
    upproj_kernel<<<dim3(40, 32), 128, GEMM_SMEM>>>(p_p1, p_wh, p_k, p_q, p_qr, p_vt);

    // 3. RoPE
    rope_kernel<<<dim3((MROWS * NHEADS * 32) / 256, 2), 256>>>();

    // 4. causal flash attention (fp16 mma)
    flash_f16_kernel<<<dim3(S_LEN / 128, BATCH * NHEADS), 256, FLASH_SMEM>>>(
        p_q, p_k, p_vt, p_y);

    // 5. output projection: [4096,2048] @ [2048,2048] -> out (f32)
    f16_gemm_kernel<<<dim3(16, 32), 128, GEMM_SMEM>>>(
        p_y, HDIM, p_wh + WO_OFF, 2048, out, HDIM, 2048, 2);
}